// round 1
// baseline (speedup 1.0000x reference)
#include <cuda_runtime.h>
#include <math.h>

#define Tlen 2048
#define Bdim 16
#define Hdim 1024
#define NLay 4
#define N3H  3072   // 3*H

// Scratch (device globals: allocation-free rule)
__device__ float g_U [(size_t)Tlen * Bdim * N3H];   // 402 MB: U = x @ W_l
__device__ float g_X0[(size_t)Tlen * Bdim * Hdim];  // 134 MB ping
__device__ float g_X1[(size_t)Tlen * Bdim * Hdim];  // 134 MB pong
__device__ float g_U0[N3H];                          // layer-0 GEMV result

// ---------------------------------------------------------------------------
// Layer-0 U: every input row is inp_vec, so U row is a single GEMV result.
// ---------------------------------------------------------------------------
__global__ void gemv_u0(const float* __restrict__ inp, const float* __restrict__ W0) {
    int k = blockIdx.x * 256 + threadIdx.x;   // 0..3071
    float s = 0.f;
#pragma unroll 8
    for (int h = 0; h < Hdim; h++)
        s = fmaf(inp[h], W0[(size_t)h * N3H + k], s);
    g_U0[k] = s;
}

// ---------------------------------------------------------------------------
// 128x128x8 double-buffered SGEMM: C[M,N] = A[M,K] * B[K,N], all row-major.
// M=32768, N=3072, K=1024 (all tile-divisible; no bounds checks).
// ---------------------------------------------------------------------------
__global__ void __launch_bounds__(256, 2) sgemm128x128(
    const float* __restrict__ A, const float* __restrict__ B,
    float* __restrict__ C, int M, int N, int K)
{
    __shared__ float As[2][8][128];
    __shared__ float Bs[2][8][128];

    const int tid = threadIdx.x;
    const int m0 = blockIdx.y * 128;
    const int n0 = blockIdx.x * 128;

    // global->smem load mapping (one float4 per thread per tile per matrix)
    const int arow = tid >> 1;            // 0..127
    const int acol = (tid & 1) * 4;       // 0 or 4
    const int brow = tid >> 5;            // 0..7
    const int bcol = (tid & 31) * 4;      // 0..124

    const float* Ap = A + (size_t)(m0 + arow) * K + acol;
    const float* Bp = B + (size_t)brow * N + n0 + bcol;

    float4 av = *(const float4*)Ap;
    float4 bv = *(const float4*)Bp;
    As[0][acol + 0][arow] = av.x;
    As[0][acol + 1][arow] = av.y;
    As[0][acol + 2][arow] = av.z;
    As[0][acol + 3][arow] = av.w;
    *(float4*)&Bs[0][brow][bcol] = bv;
    __syncthreads();

    const int ty = tid >> 4;   // 0..15 -> row block of 8
    const int tx = tid & 15;   // 0..15 -> col block of 8

    float acc[8][8];
#pragma unroll
    for (int i = 0; i < 8; i++)
#pragma unroll
        for (int j = 0; j < 8; j++) acc[i][j] = 0.f;

    int buf = 0;
    for (int kt = 8;; kt += 8) {
        const bool last = (kt >= K);
        if (!last) {
            av = *(const float4*)(Ap + kt);
            bv = *(const float4*)(Bp + (size_t)kt * N);
        }
#pragma unroll
        for (int k = 0; k < 8; k++) {
            float a[8], b[8];
            *(float4*)&a[0] = *(const float4*)&As[buf][k][ty * 8];
            *(float4*)&a[4] = *(const float4*)&As[buf][k][ty * 8 + 4];
            *(float4*)&b[0] = *(const float4*)&Bs[buf][k][tx * 8];
            *(float4*)&b[4] = *(const float4*)&Bs[buf][k][tx * 8 + 4];
#pragma unroll
            for (int i = 0; i < 8; i++)
#pragma unroll
                for (int j = 0; j < 8; j++)
                    acc[i][j] = fmaf(a[i], b[j], acc[i][j]);
        }
        if (last) break;
        buf ^= 1;
        As[buf][acol + 0][arow] = av.x;
        As[buf][acol + 1][arow] = av.y;
        As[buf][acol + 2][arow] = av.z;
        As[buf][acol + 3][arow] = av.w;
        *(float4*)&Bs[buf][brow][bcol] = bv;
        __syncthreads();
    }

    float* Cp = C + (size_t)(m0 + ty * 8) * N + n0 + tx * 8;
#pragma unroll
    for (int i = 0; i < 8; i++) {
        *(float4*)(Cp + (size_t)i * N)     = make_float4(acc[i][0], acc[i][1], acc[i][2], acc[i][3]);
        *(float4*)(Cp + (size_t)i * N + 4) = make_float4(acc[i][4], acc[i][5], acc[i][6], acc[i][7]);
    }
}

// ---------------------------------------------------------------------------
// SRU scan: 16384 independent (b,h) recurrences over t. c lives in a register.
// L0: U/x are broadcast vectors (layer 0). FINAL: write [B,T,H] into d_out.
// ---------------------------------------------------------------------------
template <bool L0, bool FINAL>
__global__ void scan_kernel(const float* __restrict__ U, const float* __restrict__ Xin,
                            const float* __restrict__ c0,
                            const float* __restrict__ Vl, const float* __restrict__ bl,
                            float* __restrict__ out)
{
    const int idx = blockIdx.x * blockDim.x + threadIdx.x;   // < B*H
    const int b = idx >> 10;
    const int h = idx & 1023;

    float c  = c0[idx];
    const float vf = Vl[h],        vr = Vl[Hdim + h];
    const float bf = bl[h],        br = bl[Hdim + h];

    float u0c = 0.f, u1c = 0.f, u2c = 0.f, xc = 0.f;
    if (L0) { u0c = U[h]; u1c = U[Hdim + h]; u2c = U[2 * Hdim + h]; xc = Xin[h]; }

#pragma unroll 4
    for (int t = 0; t < Tlen; t++) {
        float u0, u1, u2, xt;
        if (L0) {
            u0 = u0c; u1 = u1c; u2 = u2c; xt = xc;
        } else {
            const size_t base = ((size_t)t * Bdim + b) * N3H + h;
            u0 = U[base];
            u1 = U[base + Hdim];
            u2 = U[base + 2 * Hdim];
            xt = Xin[((size_t)t * Bdim + b) * Hdim + h];
        }
        const float f = 1.f / (1.f + expf(-(u1 + vf * c + bf)));
        c = f * c + (1.f - f) * u0;
        const float r = 1.f / (1.f + expf(-(u2 + vr * c + br)));
        const float hv = r * c + (1.f - r) * xt;

        const size_t oidx = FINAL ? ((size_t)b * Tlen + t) * Hdim + h
                                  : ((size_t)t * Bdim + b) * Hdim + h;
        out[oidx] = hv;
    }
}

// ---------------------------------------------------------------------------
extern "C" void kernel_launch(void* const* d_in, const int* in_sizes, int n_in,
                              void* d_out, int out_size)
{
    const float* c_n  = (const float*)d_in[0];
    // d_in[1] = max_len (int32 scalar) — fixed at 2048, hardcoded
    const float* inp  = (const float*)d_in[2];
    const float* W    = (const float*)d_in[3];   // [NL, H, 3H]
    const float* V    = (const float*)d_in[4];   // [NL, 2H]
    const float* bias = (const float*)d_in[5];   // [NL, 2H]
    float* out = (float*)d_out;

    float *pU, *pX0, *pX1, *pU0;
    cudaGetSymbolAddress((void**)&pU,  g_U);
    cudaGetSymbolAddress((void**)&pX0, g_X0);
    cudaGetSymbolAddress((void**)&pX1, g_X1);
    cudaGetSymbolAddress((void**)&pU0, g_U0);

    // Layer 0: GEMV (all GEMM rows identical) + scan -> X0
    gemv_u0<<<N3H / 256, 256>>>(inp, W);
    scan_kernel<true, false><<<(Bdim * Hdim) / 256, 256>>>(pU0, inp, c_n, V, bias, pX0);

    const float* xin = pX0;
    float*       xout = pX1;
    for (int l = 1; l < NLay; l++) {
        dim3 grid(N3H / 128, (Tlen * Bdim) / 128);
        sgemm128x128<<<grid, 256>>>(xin, W + (size_t)l * Hdim * N3H, pU,
                                    Tlen * Bdim, N3H, Hdim);
        const float* Vl = V + (size_t)l * 2 * Hdim;
        const float* bl = bias + (size_t)l * 2 * Hdim;
        if (l == NLay - 1) {
            scan_kernel<false, true><<<(Bdim * Hdim) / 256, 256>>>(pU, xin, c_n, Vl, bl, out);
        } else {
            scan_kernel<false, false><<<(Bdim * Hdim) / 256, 256>>>(pU, xin, c_n, Vl, bl, xout);
            const float* t = xin; xin = xout; xout = (float*)t;
        }
    }
}

// round 4
// speedup vs baseline: 2.1384x; 2.1384x over previous
#include <cuda_runtime.h>
#include <cstdint>
#include <math.h>

#define Tlen 2048
#define Bdim 16
#define Hdim 1024
#define NLay 4
#define N3H  3072
#define Mrows (Tlen * Bdim)      // 32768

// ---------------- device scratch (no allocs allowed) ----------------
__device__ float g_U [(size_t)Mrows * N3H];        // U = x @ W_l
__device__ float g_X0[(size_t)Mrows * Hdim];
__device__ float g_X1[(size_t)Mrows * Hdim];
__device__ float g_U0p[8 * N3H];                    // layer-0 gemv partials

// ---------------- PTX helpers ----------------
__device__ __forceinline__ uint32_t smem_u32(const void* p) {
    uint32_t a;
    asm("{ .reg .u64 t; cvta.to.shared.u64 t, %1; cvt.u32.u64 %0, t; }" : "=r"(a) : "l"(p));
    return a;
}
#define CP_ASYNC16(dst, src) \
    asm volatile("cp.async.cg.shared.global [%0], [%1], 16;" :: "r"(dst), "l"(src) : "memory")
#define CP_COMMIT()   asm volatile("cp.async.commit_group;" ::: "memory")
#define CP_WAIT(n)    asm volatile("cp.async.wait_group %0;" :: "n"(n) : "memory")

__device__ __forceinline__ uint32_t to_tf32(float x) {
    uint32_t y;
    asm("cvt.rna.tf32.f32 %0, %1;" : "=r"(y) : "f"(x));
    return y;
}
__device__ __forceinline__ void mma_tf32(float* d, const uint32_t* a, const uint32_t* b) {
    asm volatile(
        "mma.sync.aligned.m16n8k8.row.col.f32.tf32.tf32.f32 "
        "{%0,%1,%2,%3}, {%4,%5,%6,%7}, {%8,%9}, {%0,%1,%2,%3};"
        : "+f"(d[0]), "+f"(d[1]), "+f"(d[2]), "+f"(d[3])
        : "r"(a[0]), "r"(a[1]), "r"(a[2]), "r"(a[3]), "r"(b[0]), "r"(b[1]));
}

// ---------------- layer-0 GEMV partials ----------------
__global__ void gemv_partial(const float* __restrict__ inp, const float* __restrict__ W0) {
    const int k = blockIdx.x * 128 + threadIdx.x;
    const int h0 = blockIdx.y * 128;
    float s = 0.f;
#pragma unroll 8
    for (int h = 0; h < 128; h++)
        s = fmaf(inp[h0 + h], W0[(size_t)(h0 + h) * N3H + k], s);
    g_U0p[blockIdx.y * N3H + k] = s;
}

// ---------------- tf32 mma.sync GEMM ----------------
// C[M,N] = A[M,K] * B[K,N];  M=32768, N=3072, K=1024.
// CTA tile 128x128, 8 warps (2 m x 4 n), warp tile 64x32, K-chunk 32, 2-stage cp.async.
#define AS_STRIDE 36     // floats per A smem row (32 + pad 4)
#define BS_STRIDE 136    // floats per B smem row (128 + pad 8)
#define AS_STAGE  (128 * AS_STRIDE)   // 4608 floats
#define BS_STAGE  (32 * BS_STRIDE)    // 4352 floats
#define GEMM_SMEM ((2 * AS_STAGE + 2 * BS_STAGE) * 4)   // 71680 bytes

__global__ void __launch_bounds__(256, 2) gemm_tf32mma(
    const float* __restrict__ A, const float* __restrict__ B, float* __restrict__ C)
{
    extern __shared__ float smem[];
    float* As = smem;                   // [2][128][36]
    float* Bs = smem + 2 * AS_STAGE;    // [2][32][136]
    const uint32_t sbA = smem_u32(As);
    const uint32_t sbB = smem_u32(Bs);

    const int tid = threadIdx.x;
    const int n0 = blockIdx.x * 128;
    const int m0 = blockIdx.y * 128;
    const int wid = tid >> 5, lane = tid & 31;
    const int wm = wid & 1, wn = wid >> 1;       // warp tile: rows wm*64, cols wn*32
    const int g = lane >> 2, tg = lane & 3;

    const float* Ag = A + (size_t)m0 * 1024;
    const float* Bg = B + n0;

    auto load_chunk = [&](int kc, int s) {
        const int koff = kc * 32;
        // A: 128 rows x 32 floats (8 float4/row); 256 thr x 4 iters
        const int ar = tid >> 3, ac4 = tid & 7;
#pragma unroll
        for (int i = 0; i < 4; i++) {
            const int row = ar + 32 * i;
            CP_ASYNC16(sbA + (s * AS_STAGE + row * AS_STRIDE + 4 * ac4) * 4,
                       Ag + (size_t)row * 1024 + koff + 4 * ac4);
        }
        // B: 32 rows x 128 floats (32 float4/row); 256 thr x 4 iters
        const int br = tid >> 5, bc4 = tid & 31;
#pragma unroll
        for (int i = 0; i < 4; i++) {
            const int row = br + 8 * i;
            CP_ASYNC16(sbB + (s * BS_STAGE + row * BS_STRIDE + 4 * bc4) * 4,
                       Bg + (size_t)(koff + row) * N3H + 4 * bc4);
        }
        CP_COMMIT();
    };

    float acc[4][4][4];
#pragma unroll
    for (int i = 0; i < 4; i++)
#pragma unroll
        for (int j = 0; j < 4; j++)
#pragma unroll
            for (int q = 0; q < 4; q++) acc[i][j][q] = 0.f;

    load_chunk(0, 0);

    for (int c = 0; c < 32; c++) {
        const int s = c & 1;
        if (c + 1 < 32) load_chunk(c + 1, (c + 1) & 1);
        if (c + 1 < 32) { CP_WAIT(1); } else { CP_WAIT(0); }
        __syncthreads();

        const float* as = As + s * AS_STAGE + (wm * 64 + g) * AS_STRIDE;
        const float* bs = Bs + s * BS_STAGE + wn * 32 + g;
#pragma unroll
        for (int ks = 0; ks < 4; ks++) {
            const int kb = ks * 8;
            uint32_t af[4][4], bf[4][2];
#pragma unroll
            for (int mt = 0; mt < 4; mt++) {
                const float* ap = as + mt * 16 * AS_STRIDE + kb;
                af[mt][0] = to_tf32(ap[tg]);
                af[mt][1] = to_tf32(ap[8 * AS_STRIDE + tg]);
                af[mt][2] = to_tf32(ap[tg + 4]);
                af[mt][3] = to_tf32(ap[8 * AS_STRIDE + tg + 4]);
            }
#pragma unroll
            for (int nt = 0; nt < 4; nt++) {
                const float* bp = bs + (kb + tg) * BS_STRIDE + nt * 8;
                bf[nt][0] = to_tf32(bp[0]);
                bf[nt][1] = to_tf32(bp[4 * BS_STRIDE]);
            }
#pragma unroll
            for (int mt = 0; mt < 4; mt++)
#pragma unroll
                for (int nt = 0; nt < 4; nt++)
                    mma_tf32(acc[mt][nt], af[mt], bf[nt]);
        }
        __syncthreads();
    }

    // epilogue
#pragma unroll
    for (int mt = 0; mt < 4; mt++) {
        const int row = m0 + wm * 64 + mt * 16 + g;
        float* Cp0 = C + (size_t)row * N3H + n0 + wn * 32 + 2 * tg;
        float* Cp1 = Cp0 + (size_t)8 * N3H;
#pragma unroll
        for (int nt = 0; nt < 4; nt++) {
            *(float2*)(Cp0 + nt * 8) = make_float2(acc[mt][nt][0], acc[mt][nt][1]);
            *(float2*)(Cp1 + nt * 8) = make_float2(acc[mt][nt][2], acc[mt][nt][3]);
        }
    }
}

// ---------------- SRU scan ----------------
template <bool L0, bool FINAL>
__global__ void scan_kernel(const float* __restrict__ U, const float* __restrict__ Xin,
                            const float* __restrict__ c0,
                            const float* __restrict__ Vl, const float* __restrict__ bl,
                            float* __restrict__ out)
{
    const int idx = blockIdx.x * blockDim.x + threadIdx.x;   // < B*H
    const int b = idx >> 10;
    const int h = idx & 1023;

    float c  = c0[idx];
    const float vf = Vl[h], vr = Vl[Hdim + h];
    const float bf = bl[h], br = bl[Hdim + h];

    float u0c = 0.f, u1c = 0.f, u2c = 0.f, xc = 0.f;
    if (L0) {
#pragma unroll
        for (int p = 0; p < 8; p++) {
            u0c += U[p * N3H + h];
            u1c += U[p * N3H + Hdim + h];
            u2c += U[p * N3H + 2 * Hdim + h];
        }
        xc = Xin[h];
    }

#pragma unroll 4
    for (int t = 0; t < Tlen; t++) {
        float u0, u1, u2, xt;
        if (L0) {
            u0 = u0c; u1 = u1c; u2 = u2c; xt = xc;
        } else {
            const size_t base = ((size_t)t * Bdim + b) * N3H + h;
            u0 = U[base];
            u1 = U[base + Hdim];
            u2 = U[base + 2 * Hdim];
            xt = Xin[((size_t)t * Bdim + b) * Hdim + h];
        }
        const float f = 1.f / (1.f + expf(-(u1 + vf * c + bf)));
        c = f * c + (1.f - f) * u0;
        const float r = 1.f / (1.f + expf(-(u2 + vr * c + br)));
        const float hv = r * c + (1.f - r) * xt;

        const size_t oidx = FINAL ? ((size_t)b * Tlen + t) * Hdim + h
                                  : ((size_t)t * Bdim + b) * Hdim + h;
        out[oidx] = hv;
    }
}

// ---------------------------------------------------------------------------
extern "C" void kernel_launch(void* const* d_in, const int* in_sizes, int n_in,
                              void* d_out, int out_size)
{
    const float* c_n  = (const float*)d_in[0];
    const float* inp  = (const float*)d_in[2];
    const float* W    = (const float*)d_in[3];
    const float* V    = (const float*)d_in[4];
    const float* bias = (const float*)d_in[5];
    float* out = (float*)d_out;

    float *pU, *pX0, *pX1, *pU0p;
    cudaGetSymbolAddress((void**)&pU,   g_U);
    cudaGetSymbolAddress((void**)&pX0,  g_X0);
    cudaGetSymbolAddress((void**)&pX1,  g_X1);
    cudaGetSymbolAddress((void**)&pU0p, g_U0p);

    cudaFuncSetAttribute(gemm_tf32mma, cudaFuncAttributeMaxDynamicSharedMemorySize, GEMM_SMEM);

    gemv_partial<<<dim3(N3H / 128, 8), 128>>>(inp, W);
    scan_kernel<true, false><<<(Bdim * Hdim) / 128, 128>>>(pU0p, inp, c_n, V, bias, pX0);

    const float* xin = pX0;
    float*       xout = pX1;
    for (int l = 1; l < NLay; l++) {
        gemm_tf32mma<<<dim3(N3H / 128, Mrows / 128), 256, GEMM_SMEM>>>(
            xin, W + (size_t)l * Hdim * N3H, pU);
        const float* Vl = V + (size_t)l * 2 * Hdim;
        const float* bl = bias + (size_t)l * 2 * Hdim;
        if (l == NLay - 1) {
            scan_kernel<false, true><<<(Bdim * Hdim) / 128, 128>>>(pU, xin, c_n, Vl, bl, out);
        } else {
            scan_kernel<false, false><<<(Bdim * Hdim) / 128, 128>>>(pU, xin, c_n, Vl, bl, xout);
            const float* t = xin; xin = xout; xout = (float*)t;
        }
    }
}

// round 6
// speedup vs baseline: 2.2026x; 1.0300x over previous
#include <cuda_runtime.h>
#include <cstdint>
#include <math.h>

#define Tlen 2048
#define Bdim 16
#define Hdim 1024
#define NLay 4
#define N3H  3072
#define Mrows (Tlen * Bdim)      // 32768

// ---------------- device scratch (no allocs allowed) ----------------
__device__ float g_U  [(size_t)Mrows * N3H];        // U = x @ W_l
__device__ float g_X0 [(size_t)Mrows * Hdim];       // fp32 x ping
__device__ float g_X1 [(size_t)Mrows * Hdim];       // fp32 x pong
__device__ float g_Xr0[(size_t)Mrows * Hdim];       // tf32-rounded x ping
__device__ float g_Xr1[(size_t)Mrows * Hdim];       // tf32-rounded x pong
__device__ float g_Wr [(size_t)3 * Hdim * N3H];     // tf32-rounded W[1..3]
__device__ float g_U0p[8 * N3H];                     // layer-0 gemv partials

// ---------------- PTX helpers ----------------
__device__ __forceinline__ uint32_t smem_u32(const void* p) {
    uint32_t a;
    asm("{ .reg .u64 t; cvta.to.shared.u64 t, %1; cvt.u32.u64 %0, t; }" : "=r"(a) : "l"(p));
    return a;
}
#define CP_ASYNC16(dst, src) \
    asm volatile("cp.async.cg.shared.global [%0], [%1], 16;" :: "r"(dst), "l"(src) : "memory")
#define CP_COMMIT()   asm volatile("cp.async.commit_group;" ::: "memory")
#define CP_WAIT(n)    asm volatile("cp.async.wait_group %0;" :: "n"(n) : "memory")

__device__ __forceinline__ uint32_t to_tf32(float x) {
    uint32_t y;
    asm("cvt.rna.tf32.f32 %0, %1;" : "=r"(y) : "f"(x));
    return y;
}
__device__ __forceinline__ void mma_tf32(float* d, const uint32_t* a, const uint32_t* b) {
    asm volatile(
        "mma.sync.aligned.m16n8k8.row.col.f32.tf32.tf32.f32 "
        "{%0,%1,%2,%3}, {%4,%5,%6,%7}, {%8,%9}, {%0,%1,%2,%3};"
        : "+f"(d[0]), "+f"(d[1]), "+f"(d[2]), "+f"(d[3])
        : "r"(a[0]), "r"(a[1]), "r"(a[2]), "r"(a[3]), "r"(b[0]), "r"(b[1]));
}

// ---------------- W pre-round: W[1..3] -> tf32 bits ----------------
__global__ void round_w(const float* __restrict__ W, float* __restrict__ Wr) {
    const size_t i = (size_t)blockIdx.x * 256 + threadIdx.x;
    const uint32_t r = to_tf32(W[(size_t)Hdim * N3H + i]);
    Wr[i] = __uint_as_float(r);
}

// ---------------- layer-0 GEMV partials ----------------
__global__ void gemv_partial(const float* __restrict__ inp, const float* __restrict__ W0) {
    const int k = blockIdx.x * 128 + threadIdx.x;
    const int h0 = blockIdx.y * 128;
    float s = 0.f;
#pragma unroll 8
    for (int h = 0; h < 128; h++)
        s = fmaf(inp[h0 + h], W0[(size_t)(h0 + h) * N3H + k], s);
    g_U0p[blockIdx.y * N3H + k] = s;
}

// ---------------- tf32 mma.sync GEMM (pre-rounded operands) ----------------
// C[M,N] = A[M,K] * B[K,N];  M=32768, N=3072, K=1024.
// CTA tile 128x128, 8 warps (2 m x 4 n), warp tile 64x32, K-chunk 32, 2-stage cp.async.
#define AS_STRIDE 36     // floats per A smem row (32 + pad 4)
#define BS_STRIDE 136    // floats per B smem row (128 + pad 8)
#define AS_STAGE  (128 * AS_STRIDE)   // 4608 floats
#define BS_STAGE  (32 * BS_STRIDE)    // 4352 floats
#define GEMM_SMEM ((2 * AS_STAGE + 2 * BS_STAGE) * 4)   // 71680 bytes

__global__ void __launch_bounds__(256, 2) gemm_tf32mma(
    const float* __restrict__ A, const float* __restrict__ B, float* __restrict__ C)
{
    extern __shared__ float smem[];
    float* As = smem;                   // [2][128][36]
    float* Bs = smem + 2 * AS_STAGE;    // [2][32][136]
    const uint32_t sbA = smem_u32(As);
    const uint32_t sbB = smem_u32(Bs);

    const int tid = threadIdx.x;
    const int n0 = blockIdx.x * 128;
    const int m0 = blockIdx.y * 128;
    const int wid = tid >> 5, lane = tid & 31;
    const int wm = wid & 1, wn = wid >> 1;       // warp tile: rows wm*64, cols wn*32
    const int g = lane >> 2, tg = lane & 3;

    const float* Ag = A + (size_t)m0 * 1024;
    const float* Bg = B + n0;

    auto load_chunk = [&](int kc, int s) {
        const int koff = kc * 32;
        const int ar = tid >> 3, ac4 = tid & 7;
#pragma unroll
        for (int i = 0; i < 4; i++) {
            const int row = ar + 32 * i;
            CP_ASYNC16(sbA + (s * AS_STAGE + row * AS_STRIDE + 4 * ac4) * 4,
                       Ag + (size_t)row * 1024 + koff + 4 * ac4);
        }
        const int br = tid >> 5, bc4 = tid & 31;
#pragma unroll
        for (int i = 0; i < 4; i++) {
            const int row = br + 8 * i;
            CP_ASYNC16(sbB + (s * BS_STAGE + row * BS_STRIDE + 4 * bc4) * 4,
                       Bg + (size_t)(koff + row) * N3H + 4 * bc4);
        }
        CP_COMMIT();
    };

    float acc[4][4][4];
#pragma unroll
    for (int i = 0; i < 4; i++)
#pragma unroll
        for (int j = 0; j < 4; j++)
#pragma unroll
            for (int q = 0; q < 4; q++) acc[i][j][q] = 0.f;

    load_chunk(0, 0);

    for (int c = 0; c < 32; c++) {
        const int s = c & 1;
        if (c + 1 < 32) load_chunk(c + 1, (c + 1) & 1);
        if (c + 1 < 32) { CP_WAIT(1); } else { CP_WAIT(0); }
        __syncthreads();

        const uint32_t* as = (const uint32_t*)(As + s * AS_STAGE + (wm * 64 + g) * AS_STRIDE);
        const uint32_t* bs = (const uint32_t*)(Bs + s * BS_STAGE + wn * 32 + g);
#pragma unroll
        for (int ks = 0; ks < 4; ks++) {
            const int kb = ks * 8;
            uint32_t af[4][4], bf[4][2];
#pragma unroll
            for (int mt = 0; mt < 4; mt++) {
                const uint32_t* ap = as + mt * 16 * AS_STRIDE + kb;
                af[mt][0] = ap[tg];
                af[mt][1] = ap[8 * AS_STRIDE + tg];
                af[mt][2] = ap[tg + 4];
                af[mt][3] = ap[8 * AS_STRIDE + tg + 4];
            }
#pragma unroll
            for (int nt = 0; nt < 4; nt++) {
                const uint32_t* bp = bs + (kb + tg) * BS_STRIDE + nt * 8;
                bf[nt][0] = bp[0];
                bf[nt][1] = bp[4 * BS_STRIDE];
            }
#pragma unroll
            for (int mt = 0; mt < 4; mt++)
#pragma unroll
                for (int nt = 0; nt < 4; nt++)
                    mma_tf32(acc[mt][nt], af[mt], bf[nt]);
        }
        __syncthreads();
    }

    // epilogue
#pragma unroll
    for (int mt = 0; mt < 4; mt++) {
        const int row = m0 + wm * 64 + mt * 16 + g;
        float* Cp0 = C + (size_t)row * N3H + n0 + wn * 32 + 2 * tg;
        float* Cp1 = Cp0 + (size_t)8 * N3H;
#pragma unroll
        for (int nt = 0; nt < 4; nt++) {
            *(float2*)(Cp0 + nt * 8) = make_float2(acc[mt][nt][0], acc[mt][nt][1]);
            *(float2*)(Cp1 + nt * 8) = make_float2(acc[mt][nt][2], acc[mt][nt][3]);
        }
    }
}

// ---------------- SRU scan ----------------
// Writes fp32 h to `out`; if !FINAL also writes tf32-rounded h to `outr`
// (A operand of the next layer's GEMM).
template <bool L0, bool FINAL>
__global__ void scan_kernel(const float* __restrict__ U, const float* __restrict__ Xin,
                            const float* __restrict__ c0,
                            const float* __restrict__ Vl, const float* __restrict__ bl,
                            float* __restrict__ out, float* __restrict__ outr)
{
    const int idx = blockIdx.x * blockDim.x + threadIdx.x;   // < B*H
    const int b = idx >> 10;
    const int h = idx & 1023;

    float c  = c0[idx];
    const float vf = Vl[h], vr = Vl[Hdim + h];
    const float bf = bl[h], br = bl[Hdim + h];

    float u0c = 0.f, u1c = 0.f, u2c = 0.f, xc = 0.f;
    if (L0) {
#pragma unroll
        for (int p = 0; p < 8; p++) {
            u0c += U[p * N3H + h];
            u1c += U[p * N3H + Hdim + h];
            u2c += U[p * N3H + 2 * Hdim + h];
        }
        xc = Xin[h];
    }

#pragma unroll 4
    for (int t = 0; t < Tlen; t++) {
        float u0, u1, u2, xt;
        if (L0) {
            u0 = u0c; u1 = u1c; u2 = u2c; xt = xc;
        } else {
            const size_t base = ((size_t)t * Bdim + b) * N3H + h;
            u0 = U[base];
            u1 = U[base + Hdim];
            u2 = U[base + 2 * Hdim];
            xt = Xin[((size_t)t * Bdim + b) * Hdim + h];
        }
        const float f = 1.f / (1.f + expf(-(u1 + vf * c + bf)));
        c = f * c + (1.f - f) * u0;
        const float r = 1.f / (1.f + expf(-(u2 + vr * c + br)));
        const float hv = r * c + (1.f - r) * xt;

        const size_t oidx = FINAL ? ((size_t)b * Tlen + t) * Hdim + h
                                  : ((size_t)t * Bdim + b) * Hdim + h;
        out[oidx] = hv;
        if (!FINAL) outr[oidx] = __uint_as_float(to_tf32(hv));
    }
}

// ---------------------------------------------------------------------------
extern "C" void kernel_launch(void* const* d_in, const int* in_sizes, int n_in,
                              void* d_out, int out_size)
{
    const float* c_n  = (const float*)d_in[0];
    const float* inp  = (const float*)d_in[2];
    const float* W    = (const float*)d_in[3];
    const float* V    = (const float*)d_in[4];
    const float* bias = (const float*)d_in[5];
    float* out = (float*)d_out;

    float *pU, *pX0, *pX1, *pXr0, *pXr1, *pWr, *pU0p;
    cudaGetSymbolAddress((void**)&pU,   g_U);
    cudaGetSymbolAddress((void**)&pX0,  g_X0);
    cudaGetSymbolAddress((void**)&pX1,  g_X1);
    cudaGetSymbolAddress((void**)&pXr0, g_Xr0);
    cudaGetSymbolAddress((void**)&pXr1, g_Xr1);
    cudaGetSymbolAddress((void**)&pWr,  g_Wr);
    cudaGetSymbolAddress((void**)&pU0p, g_U0p);

    cudaFuncSetAttribute(gemm_tf32mma, cudaFuncAttributeMaxDynamicSharedMemorySize, GEMM_SMEM);

    // launch index:                                         0
    round_w<<<(3 * Hdim * N3H) / 256, 256>>>(W, pWr);
    // 1
    gemv_partial<<<dim3(N3H / 128, 8), 128>>>(inp, W);
    // 2
    scan_kernel<true, false><<<(Bdim * Hdim) / 128, 128>>>(pU0p, inp, c_n, V, bias, pX0, pXr0);

    const float* xin  = pX0;   // fp32 highway input
    const float* xinr = pXr0;  // rounded GEMM A
    float* xout  = pX1;
    float* xoutr = pXr1;
    for (int l = 1; l < NLay; l++) {
        // launches 3, 5, 7 — ncu -s 5 captures the l=2 GEMM
        gemm_tf32mma<<<dim3(N3H / 128, Mrows / 128), 256, GEMM_SMEM>>>(
            xinr, pWr + (size_t)(l - 1) * Hdim * N3H, pU);
        const float* Vl = V + (size_t)l * 2 * Hdim;
        const float* bl = bias + (size_t)l * 2 * Hdim;
        if (l == NLay - 1) {
            scan_kernel<false, true><<<(Bdim * Hdim) / 128, 128>>>(pU, xin, c_n, Vl, bl, out, nullptr);
        } else {
            scan_kernel<false, false><<<(Bdim * Hdim) / 128, 128>>>(pU, xin, c_n, Vl, bl, xout, xoutr);
            const float* t;
            t = xin;  xin  = xout;  xout  = (float*)t;
            t = xinr; xinr = xoutr; xoutr = (float*)t;
        }
    }
}

// round 8
// speedup vs baseline: 2.7791x; 1.2617x over previous
#include <cuda_runtime.h>
#include <cuda_fp16.h>
#include <cstdint>
#include <math.h>

#define Tlen 2048
#define Bdim 16
#define Hdim 1024
#define NLay 4
#define N3H  3072
#define Mrows (Tlen * Bdim)      // 32768

// ---------------- device scratch (no allocs allowed) ----------------
__device__ float  g_U  [(size_t)Mrows * N3H];       // U = x @ W_l (fp32)
__device__ float  g_X0 [(size_t)Mrows * Hdim];      // fp32 x ping (highway)
__device__ float  g_X1 [(size_t)Mrows * Hdim];      // fp32 x pong
__device__ __half g_Xh0[(size_t)Mrows * Hdim];      // fp16 x ping (GEMM A)
__device__ __half g_Xh1[(size_t)Mrows * Hdim];      // fp16 x pong
__device__ __half g_Wh [(size_t)3 * Hdim * N3H];    // fp16 W[1..3]
__device__ float  g_U0p[8 * N3H];                    // layer-0 gemv partials

// ---------------- PTX helpers ----------------
__device__ __forceinline__ uint32_t smem_u32(const void* p) {
    uint32_t a;
    asm("{ .reg .u64 t; cvta.to.shared.u64 t, %1; cvt.u32.u64 %0, t; }" : "=r"(a) : "l"(p));
    return a;
}
#define CP_ASYNC16(dst, src) \
    asm volatile("cp.async.cg.shared.global [%0], [%1], 16;" :: "r"(dst), "l"(src) : "memory")
#define CP_COMMIT()   asm volatile("cp.async.commit_group;" ::: "memory")
#define CP_WAIT(n)    asm volatile("cp.async.wait_group %0;" :: "n"(n) : "memory")

#define LDSM_X4(r0, r1, r2, r3, a) \
    asm volatile("ldmatrix.sync.aligned.m8n8.x4.shared.b16 {%0,%1,%2,%3}, [%4];" \
                 : "=r"(r0), "=r"(r1), "=r"(r2), "=r"(r3) : "r"(a))
#define LDSM_X4_T(r0, r1, r2, r3, a) \
    asm volatile("ldmatrix.sync.aligned.m8n8.x4.trans.shared.b16 {%0,%1,%2,%3}, [%4];" \
                 : "=r"(r0), "=r"(r1), "=r"(r2), "=r"(r3) : "r"(a))

__device__ __forceinline__ void mma_f16(float* d, const uint32_t* a, const uint32_t* b) {
    asm volatile(
        "mma.sync.aligned.m16n8k16.row.col.f32.f16.f16.f32 "
        "{%0,%1,%2,%3}, {%4,%5,%6,%7}, {%8,%9}, {%0,%1,%2,%3};"
        : "+f"(d[0]), "+f"(d[1]), "+f"(d[2]), "+f"(d[3])
        : "r"(a[0]), "r"(a[1]), "r"(a[2]), "r"(a[3]), "r"(b[0]), "r"(b[1]));
}

// ---------------- W -> fp16 for layers 1..3 ----------------
__global__ void round_wh(const float* __restrict__ W, __half* __restrict__ Wh) {
    const size_t i = (size_t)blockIdx.x * 256 + threadIdx.x;
    Wh[i] = __float2half_rn(W[(size_t)Hdim * N3H + i]);
}

// ---------------- layer-0 GEMV partials (fp32) ----------------
__global__ void gemv_partial(const float* __restrict__ inp, const float* __restrict__ W0) {
    const int k = blockIdx.x * 128 + threadIdx.x;
    const int h0 = blockIdx.y * 128;
    float s = 0.f;
#pragma unroll 8
    for (int h = 0; h < 128; h++)
        s = fmaf(inp[h0 + h], W0[(size_t)(h0 + h) * N3H + k], s);
    g_U0p[blockIdx.y * N3H + k] = s;
}

// ---------------- fp16 mma.sync GEMM ----------------
// C[M,N] = A[M,K] * B[K,N];  M=32768, N=3072, K=1024; A,B fp16, C fp32.
// CTA 128x128, 8 warps (2m x 4n), warp tile 64x32, K-chunk 32, 2-stage cp.async,
// ldmatrix fragment loads (A non-trans, B trans).
#define A_ST  40                  // halfs per A smem row (32 + 8 pad) = 80 B (5x16B)
#define B_ST  136                 // halfs per B smem row (128 + 8 pad) = 272 B (17x16B)
#define A_STG (128 * A_ST)        // halfs per A stage
#define B_STG (32 * B_ST)         // halfs per B stage
#define GEMM_SMEM ((2 * A_STG + 2 * B_STG) * 2)   // 37888 bytes

__global__ void __launch_bounds__(256, 2) gemm_f16mma(
    const __half* __restrict__ A, const __half* __restrict__ B, float* __restrict__ C)
{
    extern __shared__ __half sm[];
    __half* As = sm;                  // [2][128][40]
    __half* Bs = sm + 2 * A_STG;      // [2][32][136]
    const uint32_t sbA = smem_u32(As);
    const uint32_t sbB = smem_u32(Bs);

    const int tid = threadIdx.x;
    const int n0 = blockIdx.x * 128;
    const int m0 = blockIdx.y * 128;
    const int wid = tid >> 5, lane = tid & 31;
    const int wm = wid & 1, wn = wid >> 1;       // warp tile: rows wm*64, cols wn*32
    const int g = lane >> 2, tg = lane & 3;

    const __half* Ag = A + (size_t)m0 * 1024;
    const __half* Bg = B + n0;

    auto load_chunk = [&](int kc, int s) {
        const int koff = kc * 32;
        // A: 128 rows x 32 halfs (4 x 16B per row), 512 cp / 256 thr
#pragma unroll
        for (int i = 0; i < 2; i++) {
            const int idx = i * 256 + tid;
            const int row = idx >> 2, c16 = idx & 3;
            CP_ASYNC16(sbA + (s * A_STG + row * A_ST + c16 * 8) * 2,
                       Ag + (size_t)row * 1024 + koff + c16 * 8);
        }
        // B: 32 rows x 128 halfs (16 x 16B per row), 512 cp / 256 thr
#pragma unroll
        for (int i = 0; i < 2; i++) {
            const int idx = i * 256 + tid;
            const int row = idx >> 4, c16 = idx & 15;
            CP_ASYNC16(sbB + (s * B_STG + row * B_ST + c16 * 8) * 2,
                       Bg + (size_t)(koff + row) * N3H + c16 * 8);
        }
        CP_COMMIT();
    };

    // per-thread ldmatrix base offsets (in halfs)
    const int a_row = wm * 64 + (lane & 15);
    const int a_kof = (lane >> 4) * 8;
    const int b_krow = (lane & 7) + ((lane >> 3) & 1) * 8;
    const int b_ncol = (lane >> 4) * 8;

    float acc[4][4][4];
#pragma unroll
    for (int i = 0; i < 4; i++)
#pragma unroll
        for (int j = 0; j < 4; j++)
#pragma unroll
            for (int q = 0; q < 4; q++) acc[i][j][q] = 0.f;

    load_chunk(0, 0);

    for (int c = 0; c < 32; c++) {
        const int s = c & 1;
        if (c + 1 < 32) load_chunk(c + 1, (c + 1) & 1);
        if (c + 1 < 32) { CP_WAIT(1); } else { CP_WAIT(0); }
        __syncthreads();

#pragma unroll
        for (int ks = 0; ks < 2; ks++) {
            const int kb = ks * 16;
            uint32_t af[4][4], bf[4][2];
#pragma unroll
            for (int mt = 0; mt < 4; mt++) {
                const uint32_t addr = sbA +
                    (s * A_STG + (a_row + mt * 16) * A_ST + kb + a_kof) * 2;
                LDSM_X4(af[mt][0], af[mt][1], af[mt][2], af[mt][3], addr);
            }
#pragma unroll
            for (int nh = 0; nh < 2; nh++) {
                const uint32_t addr = sbB +
                    (s * B_STG + (kb + b_krow) * B_ST + wn * 32 + nh * 16 + b_ncol) * 2;
                LDSM_X4_T(bf[nh * 2][0], bf[nh * 2][1], bf[nh * 2 + 1][0], bf[nh * 2 + 1][1], addr);
            }
#pragma unroll
            for (int mt = 0; mt < 4; mt++)
#pragma unroll
                for (int nt = 0; nt < 4; nt++)
                    mma_f16(acc[mt][nt], af[mt], bf[nt]);
        }
        __syncthreads();
    }

    // epilogue: c0,c1 -> (row g, cols 2tg,2tg+1); c2,c3 -> (row g+8)
#pragma unroll
    for (int mt = 0; mt < 4; mt++) {
        const int row = m0 + wm * 64 + mt * 16 + g;
        float* Cp0 = C + (size_t)row * N3H + n0 + wn * 32 + 2 * tg;
        float* Cp1 = Cp0 + (size_t)8 * N3H;
#pragma unroll
        for (int nt = 0; nt < 4; nt++) {
            *(float2*)(Cp0 + nt * 8) = make_float2(acc[mt][nt][0], acc[mt][nt][1]);
            *(float2*)(Cp1 + nt * 8) = make_float2(acc[mt][nt][2], acc[mt][nt][3]);
        }
    }
}

// ---------------- SRU scan ----------------
// Writes fp32 h to `out`; if !FINAL also writes fp16 h to `outh` (next GEMM's A).
template <bool L0, bool FINAL>
__global__ void scan_kernel(const float* __restrict__ U, const float* __restrict__ Xin,
                            const float* __restrict__ c0,
                            const float* __restrict__ Vl, const float* __restrict__ bl,
                            float* __restrict__ out, __half* __restrict__ outh)
{
    const int idx = blockIdx.x * blockDim.x + threadIdx.x;   // < B*H
    const int b = idx >> 10;
    const int h = idx & 1023;

    float c  = c0[idx];
    const float vf = Vl[h], vr = Vl[Hdim + h];
    const float bf = bl[h], br = bl[Hdim + h];

    float u0c = 0.f, u1c = 0.f, u2c = 0.f, xc = 0.f;
    if (L0) {
#pragma unroll
        for (int p = 0; p < 8; p++) {
            u0c += U[p * N3H + h];
            u1c += U[p * N3H + Hdim + h];
            u2c += U[p * N3H + 2 * Hdim + h];
        }
        xc = Xin[h];
    }

#pragma unroll 4
    for (int t = 0; t < Tlen; t++) {
        float u0, u1, u2, xt;
        if (L0) {
            u0 = u0c; u1 = u1c; u2 = u2c; xt = xc;
        } else {
            const size_t base = ((size_t)t * Bdim + b) * N3H + h;
            u0 = U[base];
            u1 = U[base + Hdim];
            u2 = U[base + 2 * Hdim];
            xt = Xin[((size_t)t * Bdim + b) * Hdim + h];
        }
        const float f = 1.f / (1.f + expf(-(u1 + vf * c + bf)));
        c = f * c + (1.f - f) * u0;
        const float r = 1.f / (1.f + expf(-(u2 + vr * c + br)));
        const float hv = r * c + (1.f - r) * xt;

        const size_t oidx = FINAL ? ((size_t)b * Tlen + t) * Hdim + h
                                  : ((size_t)t * Bdim + b) * Hdim + h;
        out[oidx] = hv;
        if (!FINAL) outh[oidx] = __float2half_rn(hv);
    }
}

// ---------------------------------------------------------------------------
extern "C" void kernel_launch(void* const* d_in, const int* in_sizes, int n_in,
                              void* d_out, int out_size)
{
    const float* c_n  = (const float*)d_in[0];
    const float* inp  = (const float*)d_in[2];
    const float* W    = (const float*)d_in[3];
    const float* V    = (const float*)d_in[4];
    const float* bias = (const float*)d_in[5];
    float* out = (float*)d_out;

    float *pU, *pX0, *pX1, *pU0p;
    __half *pXh0, *pXh1, *pWh;
    cudaGetSymbolAddress((void**)&pU,   g_U);
    cudaGetSymbolAddress((void**)&pX0,  g_X0);
    cudaGetSymbolAddress((void**)&pX1,  g_X1);
    cudaGetSymbolAddress((void**)&pXh0, g_Xh0);
    cudaGetSymbolAddress((void**)&pXh1, g_Xh1);
    cudaGetSymbolAddress((void**)&pWh,  g_Wh);
    cudaGetSymbolAddress((void**)&pU0p, g_U0p);

    cudaFuncSetAttribute(gemm_f16mma, cudaFuncAttributeMaxDynamicSharedMemorySize, GEMM_SMEM);

    // launch 0
    round_wh<<<(3 * Hdim * N3H) / 256, 256>>>(W, pWh);
    // launch 1
    gemv_partial<<<dim3(N3H / 128, 8), 128>>>(inp, W);
    // launch 2
    scan_kernel<true, false><<<(Bdim * Hdim) / 128, 128>>>(pU0p, inp, c_n, V, bias, pX0, pXh0);

    const float*  xin  = pX0;   // fp32 highway input
    const __half* xinh = pXh0;  // fp16 GEMM A
    float*  xout  = pX1;
    __half* xouth = pXh1;
    for (int l = 1; l < NLay; l++) {
        // launches 3, 5, 7 — ncu -s 5 lands on the l=2 GEMM
        gemm_f16mma<<<dim3(N3H / 128, Mrows / 128), 256, GEMM_SMEM>>>(
            xinh, pWh + (size_t)(l - 1) * Hdim * N3H, pU);
        const float* Vl = V + (size_t)l * 2 * Hdim;
        const float* bl = bias + (size_t)l * 2 * Hdim;
        if (l == NLay - 1) {
            scan_kernel<false, true><<<(Bdim * Hdim) / 128, 128>>>(pU, xin, c_n, Vl, bl, out, nullptr);
        } else {
            scan_kernel<false, false><<<(Bdim * Hdim) / 128, 128>>>(pU, xin, c_n, Vl, bl, xout, xouth);
            const float* t;
            t = xin; xin = xout; xout = (float*)t;
            const __half* th;
            th = xinh; xinh = xouth; xouth = (__half*)th;
        }
    }
}

// round 10
// speedup vs baseline: 3.9445x; 1.4194x over previous
#include <cuda_runtime.h>
#include <cuda_fp16.h>
#include <cstdint>
#include <math.h>

#define Tlen 2048
#define Bdim 16
#define Hdim 1024
#define NLay 4
#define N3H  3072
#define Mrows (Tlen * Bdim)      // 32768

// ---------------- device scratch (no allocs allowed) ----------------
__device__ float  g_U  [(size_t)Mrows * N3H];       // U = x @ W_l (fp32)
__device__ float  g_X0 [(size_t)Mrows * Hdim];      // fp32 x ping (highway)
__device__ float  g_X1 [(size_t)Mrows * Hdim];      // fp32 x pong
__device__ __half g_Xh0[(size_t)Mrows * Hdim];      // fp16 x ping (GEMM A)
__device__ __half g_Xh1[(size_t)Mrows * Hdim];      // fp16 x pong
__device__ __half g_Wh [(size_t)3 * Hdim * N3H];    // fp16 W[1..3]
__device__ float  g_U0p[8 * N3H];                    // layer-0 gemv partials

// ---------------- PTX helpers ----------------
__device__ __forceinline__ uint32_t smem_u32(const void* p) {
    uint32_t a;
    asm("{ .reg .u64 t; cvta.to.shared.u64 t, %1; cvt.u32.u64 %0, t; }" : "=r"(a) : "l"(p));
    return a;
}
#define CP_ASYNC16(dst, src) \
    asm volatile("cp.async.cg.shared.global [%0], [%1], 16;" :: "r"(dst), "l"(src) : "memory")
#define CP_COMMIT()   asm volatile("cp.async.commit_group;" ::: "memory")
#define CP_WAIT(n)    asm volatile("cp.async.wait_group %0;" :: "n"(n) : "memory")

#define LDSM_X4(r0, r1, r2, r3, a) \
    asm volatile("ldmatrix.sync.aligned.m8n8.x4.shared.b16 {%0,%1,%2,%3}, [%4];" \
                 : "=r"(r0), "=r"(r1), "=r"(r2), "=r"(r3) : "r"(a))
#define LDSM_X4_T(r0, r1, r2, r3, a) \
    asm volatile("ldmatrix.sync.aligned.m8n8.x4.trans.shared.b16 {%0,%1,%2,%3}, [%4];" \
                 : "=r"(r0), "=r"(r1), "=r"(r2), "=r"(r3) : "r"(a))

__device__ __forceinline__ void mma_f16(float* d, const uint32_t* a, const uint32_t* b) {
    asm volatile(
        "mma.sync.aligned.m16n8k16.row.col.f32.f16.f16.f32 "
        "{%0,%1,%2,%3}, {%4,%5,%6,%7}, {%8,%9}, {%0,%1,%2,%3};"
        : "+f"(d[0]), "+f"(d[1]), "+f"(d[2]), "+f"(d[3])
        : "r"(a[0]), "r"(a[1]), "r"(a[2]), "r"(a[3]), "r"(b[0]), "r"(b[1]));
}

__device__ __forceinline__ float fast_sigmoid(float x) {
    return 1.f / (1.f + __expf(-x));
}

// ---------------- W -> fp16 for layers 1..3 ----------------
__global__ void round_wh(const float* __restrict__ W, __half* __restrict__ Wh) {
    const size_t i = (size_t)blockIdx.x * 256 + threadIdx.x;
    Wh[i] = __float2half_rn(W[(size_t)Hdim * N3H + i]);
}

// ---------------- layer-0 GEMV partials (fp32) ----------------
__global__ void gemv_partial(const float* __restrict__ inp, const float* __restrict__ W0) {
    const int k = blockIdx.x * 128 + threadIdx.x;
    const int h0 = blockIdx.y * 128;
    float s = 0.f;
#pragma unroll 8
    for (int h = 0; h < 128; h++)
        s = fmaf(inp[h0 + h], W0[(size_t)(h0 + h) * N3H + k], s);
    g_U0p[blockIdx.y * N3H + k] = s;
}

// ---------------- fp16 mma.sync GEMM ----------------
// C[M,N] = A[M,K] * B[K,N];  M=32768, N=3072, K=1024; A,B fp16, C fp32.
#define A_ST  40                  // halfs per A smem row (32 + 8 pad)
#define B_ST  136                 // halfs per B smem row (128 + 8 pad)
#define A_STG (128 * A_ST)
#define B_STG (32 * B_ST)
#define GEMM_SMEM ((2 * A_STG + 2 * B_STG) * 2)   // 37888 bytes

__global__ void __launch_bounds__(256, 2) gemm_f16mma(
    const __half* __restrict__ A, const __half* __restrict__ B, float* __restrict__ C)
{
    extern __shared__ __half sm[];
    __half* As = sm;                  // [2][128][40]
    __half* Bs = sm + 2 * A_STG;      // [2][32][136]
    const uint32_t sbA = smem_u32(As);
    const uint32_t sbB = smem_u32(Bs);

    const int tid = threadIdx.x;
    const int n0 = blockIdx.x * 128;
    const int m0 = blockIdx.y * 128;
    const int wid = tid >> 5, lane = tid & 31;
    const int wm = wid & 1, wn = wid >> 1;
    const int g = lane >> 2, tg = lane & 3;

    const __half* Ag = A + (size_t)m0 * 1024;
    const __half* Bg = B + n0;

    auto load_chunk = [&](int kc, int s) {
        const int koff = kc * 32;
#pragma unroll
        for (int i = 0; i < 2; i++) {
            const int idx = i * 256 + tid;
            const int row = idx >> 2, c16 = idx & 3;
            CP_ASYNC16(sbA + (s * A_STG + row * A_ST + c16 * 8) * 2,
                       Ag + (size_t)row * 1024 + koff + c16 * 8);
        }
#pragma unroll
        for (int i = 0; i < 2; i++) {
            const int idx = i * 256 + tid;
            const int row = idx >> 4, c16 = idx & 15;
            CP_ASYNC16(sbB + (s * B_STG + row * B_ST + c16 * 8) * 2,
                       Bg + (size_t)(koff + row) * N3H + c16 * 8);
        }
        CP_COMMIT();
    };

    const int a_row = wm * 64 + (lane & 15);
    const int a_kof = (lane >> 4) * 8;
    const int b_krow = (lane & 7) + ((lane >> 3) & 1) * 8;
    const int b_ncol = (lane >> 4) * 8;

    float acc[4][4][4];
#pragma unroll
    for (int i = 0; i < 4; i++)
#pragma unroll
        for (int j = 0; j < 4; j++)
#pragma unroll
            for (int q = 0; q < 4; q++) acc[i][j][q] = 0.f;

    load_chunk(0, 0);

    for (int c = 0; c < 32; c++) {
        const int s = c & 1;
        if (c + 1 < 32) load_chunk(c + 1, (c + 1) & 1);
        if (c + 1 < 32) { CP_WAIT(1); } else { CP_WAIT(0); }
        __syncthreads();

#pragma unroll
        for (int ks = 0; ks < 2; ks++) {
            const int kb = ks * 16;
            uint32_t af[4][4], bf[4][2];
#pragma unroll
            for (int mt = 0; mt < 4; mt++) {
                const uint32_t addr = sbA +
                    (s * A_STG + (a_row + mt * 16) * A_ST + kb + a_kof) * 2;
                LDSM_X4(af[mt][0], af[mt][1], af[mt][2], af[mt][3], addr);
            }
#pragma unroll
            for (int nh = 0; nh < 2; nh++) {
                const uint32_t addr = sbB +
                    (s * B_STG + (kb + b_krow) * B_ST + wn * 32 + nh * 16 + b_ncol) * 2;
                LDSM_X4_T(bf[nh * 2][0], bf[nh * 2][1], bf[nh * 2 + 1][0], bf[nh * 2 + 1][1], addr);
            }
#pragma unroll
            for (int mt = 0; mt < 4; mt++)
#pragma unroll
                for (int nt = 0; nt < 4; nt++)
                    mma_f16(acc[mt][nt], af[mt], bf[nt]);
        }
        __syncthreads();
    }

#pragma unroll
    for (int mt = 0; mt < 4; mt++) {
        const int row = m0 + wm * 64 + mt * 16 + g;
        float* Cp0 = C + (size_t)row * N3H + n0 + wn * 32 + 2 * tg;
        float* Cp1 = Cp0 + (size_t)8 * N3H;
#pragma unroll
        for (int nt = 0; nt < 4; nt++) {
            *(float2*)(Cp0 + nt * 8) = make_float2(acc[mt][nt][0], acc[mt][nt][1]);
            *(float2*)(Cp1 + nt * 8) = make_float2(acc[mt][nt][2], acc[mt][nt][3]);
        }
    }
}

// ---------------- SRU scan (layers 1..3): double-buffered register staging ----
// Batch UF=8 timesteps: prefetch the next batch's 32 independent loads before
// running the serial recurrence over the current batch.
#define UF 8
template <bool FINAL>
__global__ void __launch_bounds__(128) scan_pipelined(
    const float* __restrict__ U, const float* __restrict__ Xin,
    const float* __restrict__ c0,
    const float* __restrict__ Vl, const float* __restrict__ bl,
    float* __restrict__ out, __half* __restrict__ outh)
{
    const int idx = blockIdx.x * 128 + threadIdx.x;   // < B*H
    const int b = idx >> 10;
    const int h = idx & 1023;

    float c  = c0[idx];
    const float vf = Vl[h], vr = Vl[Hdim + h];
    const float bf = bl[h], br = bl[Hdim + h];

    const float* Ub = U   + (size_t)b * N3H + h;      // + t*(Bdim*N3H)
    const float* Xb = Xin + (size_t)b * Hdim + h;     // + t*(Bdim*Hdim)

    float u0b[2][UF], u1b[2][UF], u2b[2][UF], xb[2][UF];

    auto load_batch = [&](int t0, int s) {
#pragma unroll
        for (int i = 0; i < UF; i++) {
            const size_t tu = (size_t)(t0 + i) * (Bdim * N3H);
            u0b[s][i] = __ldg(Ub + tu);
            u1b[s][i] = __ldg(Ub + tu + Hdim);
            u2b[s][i] = __ldg(Ub + tu + 2 * Hdim);
            xb[s][i]  = __ldg(Xb + (size_t)(t0 + i) * (Bdim * Hdim));
        }
    };

    load_batch(0, 0);

    for (int t0 = 0; t0 < Tlen; t0 += UF) {
        const int s = (t0 / UF) & 1;
        if (t0 + UF < Tlen) load_batch(t0 + UF, s ^ 1);
#pragma unroll
        for (int i = 0; i < UF; i++) {
            const int t = t0 + i;
            const float f = fast_sigmoid(u1b[s][i] + vf * c + bf);
            c = f * c + (1.f - f) * u0b[s][i];
            const float r = fast_sigmoid(u2b[s][i] + vr * c + br);
            const float hv = r * c + (1.f - r) * xb[s][i];
            const size_t oidx = FINAL ? ((size_t)b * Tlen + t) * Hdim + h
                                      : ((size_t)t * Bdim + b) * Hdim + h;
            out[oidx] = hv;
            if (!FINAL) outh[oidx] = __float2half_rn(hv);
        }
    }
}

// ---------------- layer-0 scan: broadcast inputs, no per-t loads ----------------
__global__ void __launch_bounds__(128) scan_l0(
    const float* __restrict__ U0p, const float* __restrict__ inp,
    const float* __restrict__ c0,
    const float* __restrict__ Vl, const float* __restrict__ bl,
    float* __restrict__ out, __half* __restrict__ outh)
{
    const int idx = blockIdx.x * 128 + threadIdx.x;
    const int b = idx >> 10;
    const int h = idx & 1023;

    float c  = c0[idx];
    const float vf = Vl[h], vr = Vl[Hdim + h];
    const float bf = bl[h], br = bl[Hdim + h];

    float u0 = 0.f, u1 = 0.f, u2 = 0.f;
#pragma unroll
    for (int p = 0; p < 8; p++) {
        u0 += U0p[p * N3H + h];
        u1 += U0p[p * N3H + Hdim + h];
        u2 += U0p[p * N3H + 2 * Hdim + h];
    }
    const float xt = inp[h];

#pragma unroll 8
    for (int t = 0; t < Tlen; t++) {
        const float f = fast_sigmoid(u1 + vf * c + bf);
        c = f * c + (1.f - f) * u0;
        const float r = fast_sigmoid(u2 + vr * c + br);
        const float hv = r * c + (1.f - r) * xt;
        const size_t oidx = ((size_t)t * Bdim + b) * Hdim + h;
        out[oidx] = hv;
        outh[oidx] = __float2half_rn(hv);
    }
}

// ---------------------------------------------------------------------------
extern "C" void kernel_launch(void* const* d_in, const int* in_sizes, int n_in,
                              void* d_out, int out_size)
{
    const float* c_n  = (const float*)d_in[0];
    const float* inp  = (const float*)d_in[2];
    const float* W    = (const float*)d_in[3];
    const float* V    = (const float*)d_in[4];
    const float* bias = (const float*)d_in[5];
    float* out = (float*)d_out;

    float *pU, *pX0, *pX1, *pU0p;
    __half *pXh0, *pXh1, *pWh;
    cudaGetSymbolAddress((void**)&pU,   g_U);
    cudaGetSymbolAddress((void**)&pX0,  g_X0);
    cudaGetSymbolAddress((void**)&pX1,  g_X1);
    cudaGetSymbolAddress((void**)&pXh0, g_Xh0);
    cudaGetSymbolAddress((void**)&pXh1, g_Xh1);
    cudaGetSymbolAddress((void**)&pWh,  g_Wh);
    cudaGetSymbolAddress((void**)&pU0p, g_U0p);

    cudaFuncSetAttribute(gemm_f16mma, cudaFuncAttributeMaxDynamicSharedMemorySize, GEMM_SMEM);

    // launch 0
    round_wh<<<(3 * Hdim * N3H) / 256, 256>>>(W, pWh);
    // launch 1
    gemv_partial<<<dim3(N3H / 128, 8), 128>>>(inp, W);
    // launch 2
    scan_l0<<<(Bdim * Hdim) / 128, 128>>>(pU0p, inp, c_n, V, bias, pX0, pXh0);

    const float*  xin  = pX0;   // fp32 highway input
    const __half* xinh = pXh0;  // fp16 GEMM A
    float*  xout  = pX1;
    __half* xouth = pXh1;
    for (int l = 1; l < NLay; l++) {
        // launches 3, 5, 7 — ncu -s 5 lands on the l=2 GEMM
        gemm_f16mma<<<dim3(N3H / 128, Mrows / 128), 256, GEMM_SMEM>>>(
            xinh, pWh + (size_t)(l - 1) * Hdim * N3H, pU);
        const float* Vl = V + (size_t)l * 2 * Hdim;
        const float* bl = bias + (size_t)l * 2 * Hdim;
        if (l == NLay - 1) {
            scan_pipelined<true><<<(Bdim * Hdim) / 128, 128>>>(pU, xin, c_n, Vl, bl, out, nullptr);
        } else {
            scan_pipelined<false><<<(Bdim * Hdim) / 128, 128>>>(pU, xin, c_n, Vl, bl, xout, xouth);
            const float* t;
            t = xin; xin = xout; xout = (float*)t;
            const __half* th;
            th = xinh; xinh = xouth; xouth = (__half*)th;
        }
    }
}

// round 11
// speedup vs baseline: 4.5538x; 1.1545x over previous
#include <cuda_runtime.h>
#include <cuda_fp16.h>
#include <cstdint>
#include <math.h>

#define Tlen 2048
#define Bdim 16
#define Hdim 1024
#define NLay 4
#define N3H  3072
#define Mrows (Tlen * Bdim)      // 32768

// ---------------- device scratch (no allocs allowed) ----------------
__device__ float  g_U  [(size_t)Mrows * N3H];       // U = x @ W_l (fp32)
__device__ float  g_X0 [(size_t)Mrows * Hdim];      // fp32 x ping (highway)
__device__ float  g_X1 [(size_t)Mrows * Hdim];      // fp32 x pong
__device__ __half g_Xh0[(size_t)Mrows * Hdim];      // fp16 x ping (GEMM A)
__device__ __half g_Xh1[(size_t)Mrows * Hdim];      // fp16 x pong
__device__ __half g_Wh [(size_t)3 * Hdim * N3H];    // fp16 W[1..3]
__device__ float  g_U0p[8 * N3H];                    // layer-0 gemv partials

// ---------------- PTX helpers ----------------
__device__ __forceinline__ uint32_t smem_u32(const void* p) {
    uint32_t a;
    asm("{ .reg .u64 t; cvta.to.shared.u64 t, %1; cvt.u32.u64 %0, t; }" : "=r"(a) : "l"(p));
    return a;
}
#define CP_ASYNC16(dst, src) \
    asm volatile("cp.async.cg.shared.global [%0], [%1], 16;" :: "r"(dst), "l"(src) : "memory")
#define CP_COMMIT()   asm volatile("cp.async.commit_group;" ::: "memory")
#define CP_WAIT(n)    asm volatile("cp.async.wait_group %0;" :: "n"(n) : "memory")

#define LDSM_X4(r0, r1, r2, r3, a) \
    asm volatile("ldmatrix.sync.aligned.m8n8.x4.shared.b16 {%0,%1,%2,%3}, [%4];" \
                 : "=r"(r0), "=r"(r1), "=r"(r2), "=r"(r3) : "r"(a))
#define LDSM_X4_T(r0, r1, r2, r3, a) \
    asm volatile("ldmatrix.sync.aligned.m8n8.x4.trans.shared.b16 {%0,%1,%2,%3}, [%4];" \
                 : "=r"(r0), "=r"(r1), "=r"(r2), "=r"(r3) : "r"(a))

__device__ __forceinline__ void mma_f16(float* d, const uint32_t* a, const uint32_t* b) {
    asm volatile(
        "mma.sync.aligned.m16n8k16.row.col.f32.f16.f16.f32 "
        "{%0,%1,%2,%3}, {%4,%5,%6,%7}, {%8,%9}, {%0,%1,%2,%3};"
        : "+f"(d[0]), "+f"(d[1]), "+f"(d[2]), "+f"(d[3])
        : "r"(a[0]), "r"(a[1]), "r"(a[2]), "r"(a[3]), "r"(b[0]), "r"(b[1]));
}

// MUFU.RCP-based sigmoid: no IEEE division sequence on the serial chain.
__device__ __forceinline__ float fast_sigmoid(float x) {
    return __fdividef(1.f, 1.f + __expf(-x));
}

// ---------------- W -> fp16 for layers 1..3 ----------------
__global__ void round_wh(const float* __restrict__ W, __half* __restrict__ Wh) {
    const size_t i = (size_t)blockIdx.x * 256 + threadIdx.x;
    Wh[i] = __float2half_rn(W[(size_t)Hdim * N3H + i]);
}

// ---------------- layer-0 GEMV partials (fp32) ----------------
__global__ void gemv_partial(const float* __restrict__ inp, const float* __restrict__ W0) {
    const int k = blockIdx.x * 128 + threadIdx.x;
    const int h0 = blockIdx.y * 128;
    float s = 0.f;
#pragma unroll 8
    for (int h = 0; h < 128; h++)
        s = fmaf(inp[h0 + h], W0[(size_t)(h0 + h) * N3H + k], s);
    g_U0p[blockIdx.y * N3H + k] = s;
}

// ---------------- fp16 mma.sync GEMM ----------------
// C[M,N] = A[M,K] * B[K,N];  M=32768, N=3072, K=1024; A,B fp16, C fp32.
#define A_ST  40                  // halfs per A smem row (32 + 8 pad)
#define B_ST  136                 // halfs per B smem row (128 + 8 pad)
#define A_STG (128 * A_ST)
#define B_STG (32 * B_ST)
#define GEMM_SMEM ((2 * A_STG + 2 * B_STG) * 2)   // 37888 bytes

__global__ void __launch_bounds__(256, 2) gemm_f16mma(
    const __half* __restrict__ A, const __half* __restrict__ B, float* __restrict__ C)
{
    extern __shared__ __half sm[];
    __half* As = sm;                  // [2][128][40]
    __half* Bs = sm + 2 * A_STG;      // [2][32][136]
    const uint32_t sbA = smem_u32(As);
    const uint32_t sbB = smem_u32(Bs);

    const int tid = threadIdx.x;
    const int n0 = blockIdx.x * 128;
    const int m0 = blockIdx.y * 128;
    const int wid = tid >> 5, lane = tid & 31;
    const int wm = wid & 1, wn = wid >> 1;
    const int g = lane >> 2, tg = lane & 3;

    const __half* Ag = A + (size_t)m0 * 1024;
    const __half* Bg = B + n0;

    auto load_chunk = [&](int kc, int s) {
        const int koff = kc * 32;
#pragma unroll
        for (int i = 0; i < 2; i++) {
            const int idx = i * 256 + tid;
            const int row = idx >> 2, c16 = idx & 3;
            CP_ASYNC16(sbA + (s * A_STG + row * A_ST + c16 * 8) * 2,
                       Ag + (size_t)row * 1024 + koff + c16 * 8);
        }
#pragma unroll
        for (int i = 0; i < 2; i++) {
            const int idx = i * 256 + tid;
            const int row = idx >> 4, c16 = idx & 15;
            CP_ASYNC16(sbB + (s * B_STG + row * B_ST + c16 * 8) * 2,
                       Bg + (size_t)(koff + row) * N3H + c16 * 8);
        }
        CP_COMMIT();
    };

    const int a_row = wm * 64 + (lane & 15);
    const int a_kof = (lane >> 4) * 8;
    const int b_krow = (lane & 7) + ((lane >> 3) & 1) * 8;
    const int b_ncol = (lane >> 4) * 8;

    float acc[4][4][4];
#pragma unroll
    for (int i = 0; i < 4; i++)
#pragma unroll
        for (int j = 0; j < 4; j++)
#pragma unroll
            for (int q = 0; q < 4; q++) acc[i][j][q] = 0.f;

    load_chunk(0, 0);

    for (int c = 0; c < 32; c++) {
        const int s = c & 1;
        if (c + 1 < 32) load_chunk(c + 1, (c + 1) & 1);
        if (c + 1 < 32) { CP_WAIT(1); } else { CP_WAIT(0); }
        __syncthreads();

#pragma unroll
        for (int ks = 0; ks < 2; ks++) {
            const int kb = ks * 16;
            uint32_t af[4][4], bf[4][2];
#pragma unroll
            for (int mt = 0; mt < 4; mt++) {
                const uint32_t addr = sbA +
                    (s * A_STG + (a_row + mt * 16) * A_ST + kb + a_kof) * 2;
                LDSM_X4(af[mt][0], af[mt][1], af[mt][2], af[mt][3], addr);
            }
#pragma unroll
            for (int nh = 0; nh < 2; nh++) {
                const uint32_t addr = sbB +
                    (s * B_STG + (kb + b_krow) * B_ST + wn * 32 + nh * 16 + b_ncol) * 2;
                LDSM_X4_T(bf[nh * 2][0], bf[nh * 2][1], bf[nh * 2 + 1][0], bf[nh * 2 + 1][1], addr);
            }
#pragma unroll
            for (int mt = 0; mt < 4; mt++)
#pragma unroll
                for (int nt = 0; nt < 4; nt++)
                    mma_f16(acc[mt][nt], af[mt], bf[nt]);
        }
        __syncthreads();
    }

#pragma unroll
    for (int mt = 0; mt < 4; mt++) {
        const int row = m0 + wm * 64 + mt * 16 + g;
        float* Cp0 = C + (size_t)row * N3H + n0 + wn * 32 + 2 * tg;
        float* Cp1 = Cp0 + (size_t)8 * N3H;
#pragma unroll
        for (int nt = 0; nt < 4; nt++) {
            *(float2*)(Cp0 + nt * 8) = make_float2(acc[mt][nt][0], acc[mt][nt][1]);
            *(float2*)(Cp1 + nt * 8) = make_float2(acc[mt][nt][2], acc[mt][nt][3]);
        }
    }
}

// ---------------- SRU scan (layers 1..3): double-buffered register staging ----
#define UF 8
template <bool FINAL>
__global__ void __launch_bounds__(128) scan_pipelined(
    const float* __restrict__ U, const float* __restrict__ Xin,
    const float* __restrict__ c0,
    const float* __restrict__ Vl, const float* __restrict__ bl,
    float* __restrict__ out, __half* __restrict__ outh)
{
    const int idx = blockIdx.x * 128 + threadIdx.x;   // < B*H
    const int b = idx >> 10;
    const int h = idx & 1023;

    float c  = c0[idx];
    const float vf = Vl[h], vr = Vl[Hdim + h];
    const float bf = bl[h], br = bl[Hdim + h];

    const float* Ub = U   + (size_t)b * N3H + h;      // + t*(Bdim*N3H)
    const float* Xb = Xin + (size_t)b * Hdim + h;     // + t*(Bdim*Hdim)

    float u0b[2][UF], u1b[2][UF], u2b[2][UF], xb[2][UF];

    auto load_batch = [&](int t0, int s) {
#pragma unroll
        for (int i = 0; i < UF; i++) {
            const size_t tu = (size_t)(t0 + i) * (Bdim * N3H);
            u0b[s][i] = __ldg(Ub + tu);
            u1b[s][i] = __ldg(Ub + tu + Hdim);
            u2b[s][i] = __ldg(Ub + tu + 2 * Hdim);
            xb[s][i]  = __ldg(Xb + (size_t)(t0 + i) * (Bdim * Hdim));
        }
    };

    load_batch(0, 0);

    for (int t0 = 0; t0 < Tlen; t0 += UF) {
        const int s = (t0 / UF) & 1;
        if (t0 + UF < Tlen) load_batch(t0 + UF, s ^ 1);
#pragma unroll
        for (int i = 0; i < UF; i++) {
            const int t = t0 + i;
            const float f = fast_sigmoid(u1b[s][i] + vf * c + bf);
            c = f * c + (1.f - f) * u0b[s][i];
            const float r = fast_sigmoid(u2b[s][i] + vr * c + br);
            const float hv = r * c + (1.f - r) * xb[s][i];
            const size_t oidx = FINAL ? ((size_t)b * Tlen + t) * Hdim + h
                                      : ((size_t)t * Bdim + b) * Hdim + h;
            out[oidx] = hv;
            if (!FINAL) outh[oidx] = __float2half_rn(hv);
        }
    }
}

// ---------------- layer-0 scan: broadcast inputs, no per-t loads ----------------
__global__ void __launch_bounds__(128) scan_l0(
    const float* __restrict__ U0p, const float* __restrict__ inp,
    const float* __restrict__ c0,
    const float* __restrict__ Vl, const float* __restrict__ bl,
    float* __restrict__ out, __half* __restrict__ outh)
{
    const int idx = blockIdx.x * 128 + threadIdx.x;
    const int b = idx >> 10;
    const int h = idx & 1023;

    float c  = c0[idx];
    const float vf = Vl[h], vr = Vl[Hdim + h];
    const float bf = bl[h], br = bl[Hdim + h];

    float u0 = 0.f, u1 = 0.f, u2 = 0.f;
#pragma unroll
    for (int p = 0; p < 8; p++) {
        u0 += U0p[p * N3H + h];
        u1 += U0p[p * N3H + Hdim + h];
        u2 += U0p[p * N3H + 2 * Hdim + h];
    }
    const float xt = inp[h];

#pragma unroll 8
    for (int t = 0; t < Tlen; t++) {
        const float f = fast_sigmoid(u1 + vf * c + bf);
        c = f * c + (1.f - f) * u0;
        const float r = fast_sigmoid(u2 + vr * c + br);
        const float hv = r * c + (1.f - r) * xt;
        const size_t oidx = ((size_t)t * Bdim + b) * Hdim + h;
        out[oidx] = hv;
        outh[oidx] = __float2half_rn(hv);
    }
}

// ---------------------------------------------------------------------------
extern "C" void kernel_launch(void* const* d_in, const int* in_sizes, int n_in,
                              void* d_out, int out_size)
{
    const float* c_n  = (const float*)d_in[0];
    const float* inp  = (const float*)d_in[2];
    const float* W    = (const float*)d_in[3];
    const float* V    = (const float*)d_in[4];
    const float* bias = (const float*)d_in[5];
    float* out = (float*)d_out;

    float *pU, *pX0, *pX1, *pU0p;
    __half *pXh0, *pXh1, *pWh;
    cudaGetSymbolAddress((void**)&pU,   g_U);
    cudaGetSymbolAddress((void**)&pX0,  g_X0);
    cudaGetSymbolAddress((void**)&pX1,  g_X1);
    cudaGetSymbolAddress((void**)&pXh0, g_Xh0);
    cudaGetSymbolAddress((void**)&pXh1, g_Xh1);
    cudaGetSymbolAddress((void**)&pWh,  g_Wh);
    cudaGetSymbolAddress((void**)&pU0p, g_U0p);

    cudaFuncSetAttribute(gemm_f16mma, cudaFuncAttributeMaxDynamicSharedMemorySize, GEMM_SMEM);

    // launch 0
    round_wh<<<(3 * Hdim * N3H) / 256, 256>>>(W, pWh);
    // launch 1
    gemv_partial<<<dim3(N3H / 128, 8), 128>>>(inp, W);
    // launch 2
    scan_l0<<<(Bdim * Hdim) / 128, 128>>>(pU0p, inp, c_n, V, bias, pX0, pXh0);

    const float*  xin  = pX0;   // fp32 highway input
    const __half* xinh = pXh0;  // fp16 GEMM A
    float*  xout  = pX1;
    __half* xouth = pXh1;
    for (int l = 1; l < NLay; l++) {
        // launches 3, 5, 7 — ncu -s 5 lands on the l=2 GEMM
        gemm_f16mma<<<dim3(N3H / 128, Mrows / 128), 256, GEMM_SMEM>>>(
            xinh, pWh + (size_t)(l - 1) * Hdim * N3H, pU);
        const float* Vl = V + (size_t)l * 2 * Hdim;
        const float* bl = bias + (size_t)l * 2 * Hdim;
        if (l == NLay - 1) {
            scan_pipelined<true><<<(Bdim * Hdim) / 128, 128>>>(pU, xin, c_n, Vl, bl, out, nullptr);
        } else {
            scan_pipelined<false><<<(Bdim * Hdim) / 128, 128>>>(pU, xin, c_n, Vl, bl, xout, xouth);
            const float* t;
            t = xin; xin = xout; xout = (float*)t;
            const __half* th;
            th = xinh; xinh = xouth; xouth = (__half*)th;
        }
    }
}

// round 12
// speedup vs baseline: 5.6344x; 1.2373x over previous
#include <cuda_runtime.h>
#include <cuda_fp16.h>
#include <cstdint>
#include <math.h>

#define Tlen 2048
#define Bdim 16
#define Hdim 1024
#define NLay 4
#define N3H  3072
#define Mrows (Tlen * Bdim)      // 32768

// ---------------- device scratch (no allocs allowed) ----------------
__device__ float  g_U  [(size_t)Mrows * N3H];       // U = x @ W_l (fp32)
__device__ float  g_X0 [(size_t)Mrows * Hdim];      // fp32 x ping (highway)
__device__ float  g_X1 [(size_t)Mrows * Hdim];      // fp32 x pong
__device__ __half g_Xh0[(size_t)Mrows * Hdim];      // fp16 x ping (GEMM A)
__device__ __half g_Xh1[(size_t)Mrows * Hdim];      // fp16 x pong
__device__ __half g_Wh [(size_t)3 * Hdim * N3H];    // fp16 W[1..3]
__device__ float  g_U0p[8 * N3H];                    // layer-0 gemv partials

// ---------------- PTX helpers ----------------
__device__ __forceinline__ uint32_t smem_u32(const void* p) {
    uint32_t a;
    asm("{ .reg .u64 t; cvta.to.shared.u64 t, %1; cvt.u32.u64 %0, t; }" : "=r"(a) : "l"(p));
    return a;
}
#define CP_ASYNC16(dst, src) \
    asm volatile("cp.async.cg.shared.global [%0], [%1], 16;" :: "r"(dst), "l"(src) : "memory")
#define CP_COMMIT()   asm volatile("cp.async.commit_group;" ::: "memory")
#define CP_WAIT(n)    asm volatile("cp.async.wait_group %0;" :: "n"(n) : "memory")

#define LDSM_X4(r0, r1, r2, r3, a) \
    asm volatile("ldmatrix.sync.aligned.m8n8.x4.shared.b16 {%0,%1,%2,%3}, [%4];" \
                 : "=r"(r0), "=r"(r1), "=r"(r2), "=r"(r3) : "r"(a))
#define LDSM_X4_T(r0, r1, r2, r3, a) \
    asm volatile("ldmatrix.sync.aligned.m8n8.x4.trans.shared.b16 {%0,%1,%2,%3}, [%4];" \
                 : "=r"(r0), "=r"(r1), "=r"(r2), "=r"(r3) : "r"(a))

__device__ __forceinline__ void mma_f16(float* d, const uint32_t* a, const uint32_t* b) {
    asm volatile(
        "mma.sync.aligned.m16n8k16.row.col.f32.f16.f16.f32 "
        "{%0,%1,%2,%3}, {%4,%5,%6,%7}, {%8,%9}, {%0,%1,%2,%3};"
        : "+f"(d[0]), "+f"(d[1]), "+f"(d[2]), "+f"(d[3])
        : "r"(a[0]), "r"(a[1]), "r"(a[2]), "r"(a[3]), "r"(b[0]), "r"(b[1]));
}

// MUFU.RCP-based sigmoid: no IEEE division sequence on the serial chain.
__device__ __forceinline__ float fast_sigmoid(float x) {
    return __fdividef(1.f, 1.f + __expf(-x));
}

// ---------------- W -> fp16 for layers 1..3 ----------------
__global__ void round_wh(const float* __restrict__ W, __half* __restrict__ Wh) {
    const size_t i = (size_t)blockIdx.x * 256 + threadIdx.x;
    Wh[i] = __float2half_rn(W[(size_t)Hdim * N3H + i]);
}

// ---------------- layer-0 GEMV partials (fp32) ----------------
__global__ void gemv_partial(const float* __restrict__ inp, const float* __restrict__ W0) {
    const int k = blockIdx.x * 128 + threadIdx.x;
    const int h0 = blockIdx.y * 128;
    float s = 0.f;
#pragma unroll 8
    for (int h = 0; h < 128; h++)
        s = fmaf(inp[h0 + h], W0[(size_t)(h0 + h) * N3H + k], s);
    g_U0p[blockIdx.y * N3H + k] = s;
}

// ---------------- fp16 mma.sync GEMM, K-chunk 64 ----------------
// C[M,N] = A[M,K] * B[K,N];  M=32768, N=3072, K=1024; A,B fp16, C fp32.
// CTA 128x128, 8 warps (2m x 4n), warp tile 64x32, K-chunk 64, 2-stage cp.async.
#define A_ST  72                  // halfs per A smem row (64 + 8 pad) = 144 B (9x16B)
#define B_ST  136                 // halfs per B smem row (128 + 8 pad) = 272 B (17x16B)
#define A_STG (128 * A_ST)
#define B_STG (64 * B_ST)
#define GEMM_SMEM ((2 * A_STG + 2 * B_STG) * 2)   // 71680 bytes
#define KCH   16                  // 1024 / 64

__global__ void __launch_bounds__(256, 2) gemm_f16mma(
    const __half* __restrict__ A, const __half* __restrict__ B, float* __restrict__ C)
{
    extern __shared__ __half sm[];
    __half* As = sm;                  // [2][128][72]
    __half* Bs = sm + 2 * A_STG;      // [2][64][136]
    const uint32_t sbA = smem_u32(As);
    const uint32_t sbB = smem_u32(Bs);

    const int tid = threadIdx.x;
    const int n0 = blockIdx.x * 128;
    const int m0 = blockIdx.y * 128;
    const int wid = tid >> 5, lane = tid & 31;
    const int wm = wid & 1, wn = wid >> 1;
    const int g = lane >> 2, tg = lane & 3;

    const __half* Ag = A + (size_t)m0 * 1024;
    const __half* Bg = B + n0;

    auto load_chunk = [&](int kc, int s) {
        const int koff = kc * 64;
        // A: 128 rows x 64 halfs (8 x 16B/row) = 1024 transfers / 256 thr
#pragma unroll
        for (int i = 0; i < 4; i++) {
            const int idx = i * 256 + tid;
            const int row = idx >> 3, c16 = idx & 7;
            CP_ASYNC16(sbA + (s * A_STG + row * A_ST + c16 * 8) * 2,
                       Ag + (size_t)row * 1024 + koff + c16 * 8);
        }
        // B: 64 rows x 128 halfs (16 x 16B/row) = 1024 transfers / 256 thr
#pragma unroll
        for (int i = 0; i < 4; i++) {
            const int idx = i * 256 + tid;
            const int row = idx >> 4, c16 = idx & 15;
            CP_ASYNC16(sbB + (s * B_STG + row * B_ST + c16 * 8) * 2,
                       Bg + (size_t)(koff + row) * N3H + c16 * 8);
        }
        CP_COMMIT();
    };

    const int a_row = wm * 64 + (lane & 15);
    const int a_kof = (lane >> 4) * 8;
    const int b_krow = (lane & 7) + ((lane >> 3) & 1) * 8;
    const int b_ncol = (lane >> 4) * 8;

    float acc[4][4][4];
#pragma unroll
    for (int i = 0; i < 4; i++)
#pragma unroll
        for (int j = 0; j < 4; j++)
#pragma unroll
            for (int q = 0; q < 4; q++) acc[i][j][q] = 0.f;

    load_chunk(0, 0);

    for (int c = 0; c < KCH; c++) {
        const int s = c & 1;
        if (c + 1 < KCH) load_chunk(c + 1, (c + 1) & 1);
        if (c + 1 < KCH) { CP_WAIT(1); } else { CP_WAIT(0); }
        __syncthreads();

#pragma unroll
        for (int ks = 0; ks < 4; ks++) {
            const int kb = ks * 16;
            uint32_t af[4][4], bf[4][2];
#pragma unroll
            for (int mt = 0; mt < 4; mt++) {
                const uint32_t addr = sbA +
                    (s * A_STG + (a_row + mt * 16) * A_ST + kb + a_kof) * 2;
                LDSM_X4(af[mt][0], af[mt][1], af[mt][2], af[mt][3], addr);
            }
#pragma unroll
            for (int nh = 0; nh < 2; nh++) {
                const uint32_t addr = sbB +
                    (s * B_STG + (kb + b_krow) * B_ST + wn * 32 + nh * 16 + b_ncol) * 2;
                LDSM_X4_T(bf[nh * 2][0], bf[nh * 2][1], bf[nh * 2 + 1][0], bf[nh * 2 + 1][1], addr);
            }
#pragma unroll
            for (int mt = 0; mt < 4; mt++)
#pragma unroll
                for (int nt = 0; nt < 4; nt++)
                    mma_f16(acc[mt][nt], af[mt], bf[nt]);
        }
        __syncthreads();
    }

#pragma unroll
    for (int mt = 0; mt < 4; mt++) {
        const int row = m0 + wm * 64 + mt * 16 + g;
        float* Cp0 = C + (size_t)row * N3H + n0 + wn * 32 + 2 * tg;
        float* Cp1 = Cp0 + (size_t)8 * N3H;
#pragma unroll
        for (int nt = 0; nt < 4; nt++) {
            *(float2*)(Cp0 + nt * 8) = make_float2(acc[mt][nt][0], acc[mt][nt][1]);
            *(float2*)(Cp1 + nt * 8) = make_float2(acc[mt][nt][2], acc[mt][nt][3]);
        }
    }
}

// ---------------- SRU scan (layers 1..3) ----------------
// True register double-buffering: buffer index is a compile-time constant in
// each half of the 2*UF-unrolled loop (dynamic indexing would spill to local).
#define UF 8
template <bool FINAL>
__global__ void __launch_bounds__(128) scan_pipelined(
    const float* __restrict__ U, const float* __restrict__ Xin,
    const float* __restrict__ c0,
    const float* __restrict__ Vl, const float* __restrict__ bl,
    float* __restrict__ out, __half* __restrict__ outh)
{
    const int idx = blockIdx.x * 128 + threadIdx.x;   // < B*H
    const int b = idx >> 10;
    const int h = idx & 1023;

    float c  = c0[idx];
    const float vf = Vl[h], vr = Vl[Hdim + h];
    const float bf = bl[h], br = bl[Hdim + h];

    const float* Ub = U   + (size_t)b * N3H + h;      // + t*(Bdim*N3H)
    const float* Xb = Xin + (size_t)b * Hdim + h;     // + t*(Bdim*Hdim)

    float u0b[2][UF], u1b[2][UF], u2b[2][UF], xb[2][UF];

#define LOAD_BATCH(S, T0) do {                                               \
    _Pragma("unroll")                                                        \
    for (int i = 0; i < UF; i++) {                                           \
        const size_t tu = (size_t)((T0) + i) * (Bdim * N3H);                 \
        u0b[S][i] = __ldg(Ub + tu);                                          \
        u1b[S][i] = __ldg(Ub + tu + Hdim);                                   \
        u2b[S][i] = __ldg(Ub + tu + 2 * Hdim);                               \
        xb[S][i]  = __ldg(Xb + (size_t)((T0) + i) * (Bdim * Hdim));          \
    }                                                                        \
} while (0)

#define COMPUTE_BATCH(S, T0) do {                                            \
    _Pragma("unroll")                                                        \
    for (int i = 0; i < UF; i++) {                                           \
        const int t = (T0) + i;                                              \
        const float f = fast_sigmoid(u1b[S][i] + vf * c + bf);               \
        c = f * c + (1.f - f) * u0b[S][i];                                   \
        const float r = fast_sigmoid(u2b[S][i] + vr * c + br);               \
        const float hv = r * c + (1.f - r) * xb[S][i];                       \
        const size_t oidx = FINAL ? ((size_t)b * Tlen + t) * Hdim + h        \
                                  : ((size_t)t * Bdim + b) * Hdim + h;       \
        out[oidx] = hv;                                                      \
        if (!FINAL) outh[oidx] = __float2half_rn(hv);                        \
    }                                                                        \
} while (0)

    LOAD_BATCH(0, 0);
    for (int t0 = 0; t0 < Tlen; t0 += 2 * UF) {
        LOAD_BATCH(1, t0 + UF);                       // prefetch odd batch
        COMPUTE_BATCH(0, t0);
        if (t0 + 2 * UF < Tlen) LOAD_BATCH(0, t0 + 2 * UF);  // prefetch next even
        COMPUTE_BATCH(1, t0 + UF);
    }
#undef LOAD_BATCH
#undef COMPUTE_BATCH
}

// ---------------- layer-0 scan: broadcast inputs, no per-t loads ----------------
__global__ void __launch_bounds__(128) scan_l0(
    const float* __restrict__ U0p, const float* __restrict__ inp,
    const float* __restrict__ c0,
    const float* __restrict__ Vl, const float* __restrict__ bl,
    float* __restrict__ out, __half* __restrict__ outh)
{
    const int idx = blockIdx.x * 128 + threadIdx.x;
    const int b = idx >> 10;
    const int h = idx & 1023;

    float c  = c0[idx];
    const float vf = Vl[h], vr = Vl[Hdim + h];
    const float bf = bl[h], br = bl[Hdim + h];

    float u0 = 0.f, u1 = 0.f, u2 = 0.f;
#pragma unroll
    for (int p = 0; p < 8; p++) {
        u0 += U0p[p * N3H + h];
        u1 += U0p[p * N3H + Hdim + h];
        u2 += U0p[p * N3H + 2 * Hdim + h];
    }
    const float xt = inp[h];

#pragma unroll 8
    for (int t = 0; t < Tlen; t++) {
        const float f = fast_sigmoid(u1 + vf * c + bf);
        c = f * c + (1.f - f) * u0;
        const float r = fast_sigmoid(u2 + vr * c + br);
        const float hv = r * c + (1.f - r) * xt;
        const size_t oidx = ((size_t)t * Bdim + b) * Hdim + h;
        out[oidx] = hv;
        outh[oidx] = __float2half_rn(hv);
    }
}

// ---------------------------------------------------------------------------
extern "C" void kernel_launch(void* const* d_in, const int* in_sizes, int n_in,
                              void* d_out, int out_size)
{
    const float* c_n  = (const float*)d_in[0];
    const float* inp  = (const float*)d_in[2];
    const float* W    = (const float*)d_in[3];
    const float* V    = (const float*)d_in[4];
    const float* bias = (const float*)d_in[5];
    float* out = (float*)d_out;

    float *pU, *pX0, *pX1, *pU0p;
    __half *pXh0, *pXh1, *pWh;
    cudaGetSymbolAddress((void**)&pU,   g_U);
    cudaGetSymbolAddress((void**)&pX0,  g_X0);
    cudaGetSymbolAddress((void**)&pX1,  g_X1);
    cudaGetSymbolAddress((void**)&pXh0, g_Xh0);
    cudaGetSymbolAddress((void**)&pXh1, g_Xh1);
    cudaGetSymbolAddress((void**)&pWh,  g_Wh);
    cudaGetSymbolAddress((void**)&pU0p, g_U0p);

    cudaFuncSetAttribute(gemm_f16mma, cudaFuncAttributeMaxDynamicSharedMemorySize, GEMM_SMEM);

    // launch 0
    round_wh<<<(3 * Hdim * N3H) / 256, 256>>>(W, pWh);
    // launch 1
    gemv_partial<<<dim3(N3H / 128, 8), 128>>>(inp, W);
    // launch 2
    scan_l0<<<(Bdim * Hdim) / 128, 128>>>(pU0p, inp, c_n, V, bias, pX0, pXh0);

    const float*  xin  = pX0;   // fp32 highway input
    const __half* xinh = pXh0;  // fp16 GEMM A
    float*  xout  = pX1;
    __half* xouth = pXh1;
    for (int l = 1; l < NLay; l++) {
        // launches 3, 5, 7 — ncu -s 5 lands on the l=2 GEMM
        gemm_f16mma<<<dim3(N3H / 128, Mrows / 128), 256, GEMM_SMEM>>>(
            xinh, pWh + (size_t)(l - 1) * Hdim * N3H, pU);
        const float* Vl = V + (size_t)l * 2 * Hdim;
        const float* bl = bias + (size_t)l * 2 * Hdim;
        if (l == NLay - 1) {
            scan_pipelined<true><<<(Bdim * Hdim) / 128, 128>>>(pU, xin, c_n, Vl, bl, out, nullptr);
        } else {
            scan_pipelined<false><<<(Bdim * Hdim) / 128, 128>>>(pU, xin, c_n, Vl, bl, xout, xouth);
            const float* t;
            t = xin; xin = xout; xout = (float*)t;
            const __half* th;
            th = xinh; xinh = xouth; xouth = (__half*)th;
        }
    }
}

// round 13
// speedup vs baseline: 5.8991x; 1.0470x over previous
#include <cuda_runtime.h>
#include <cuda_fp16.h>
#include <cstdint>
#include <math.h>

#define Tlen 2048
#define Bdim 16
#define Hdim 1024
#define NLay 4
#define N3H  3072
#define Mrows (Tlen * Bdim)      // 32768

// ---------------- device scratch (no allocs allowed) ----------------
__device__ __half g_Uh [(size_t)Mrows * N3H];       // U = x @ W_l (fp16)
__device__ float  g_X0 [(size_t)Mrows * Hdim];      // fp32 x ping (highway)
__device__ float  g_X1 [(size_t)Mrows * Hdim];      // fp32 x pong
__device__ __half g_Xh0[(size_t)Mrows * Hdim];      // fp16 x ping (GEMM A)
__device__ __half g_Xh1[(size_t)Mrows * Hdim];      // fp16 x pong
__device__ __half g_Wh [(size_t)3 * Hdim * N3H];    // fp16 W[1..3]
__device__ float  g_U0p[8 * N3H];                    // layer-0 gemv partials (fp32)

// ---------------- PTX helpers ----------------
__device__ __forceinline__ uint32_t smem_u32(const void* p) {
    uint32_t a;
    asm("{ .reg .u64 t; cvta.to.shared.u64 t, %1; cvt.u32.u64 %0, t; }" : "=r"(a) : "l"(p));
    return a;
}
#define CP_ASYNC16(dst, src) \
    asm volatile("cp.async.cg.shared.global [%0], [%1], 16;" :: "r"(dst), "l"(src) : "memory")
#define CP_COMMIT()   asm volatile("cp.async.commit_group;" ::: "memory")
#define CP_WAIT(n)    asm volatile("cp.async.wait_group %0;" :: "n"(n) : "memory")

#define LDSM_X4(r0, r1, r2, r3, a) \
    asm volatile("ldmatrix.sync.aligned.m8n8.x4.shared.b16 {%0,%1,%2,%3}, [%4];" \
                 : "=r"(r0), "=r"(r1), "=r"(r2), "=r"(r3) : "r"(a))
#define LDSM_X4_T(r0, r1, r2, r3, a) \
    asm volatile("ldmatrix.sync.aligned.m8n8.x4.trans.shared.b16 {%0,%1,%2,%3}, [%4];" \
                 : "=r"(r0), "=r"(r1), "=r"(r2), "=r"(r3) : "r"(a))

__device__ __forceinline__ void mma_f16(float* d, const uint32_t* a, const uint32_t* b) {
    asm volatile(
        "mma.sync.aligned.m16n8k16.row.col.f32.f16.f16.f32 "
        "{%0,%1,%2,%3}, {%4,%5,%6,%7}, {%8,%9}, {%0,%1,%2,%3};"
        : "+f"(d[0]), "+f"(d[1]), "+f"(d[2]), "+f"(d[3])
        : "r"(a[0]), "r"(a[1]), "r"(a[2]), "r"(a[3]), "r"(b[0]), "r"(b[1]));
}

// MUFU.RCP-based sigmoid: no IEEE division sequence on the serial chain.
__device__ __forceinline__ float fast_sigmoid(float x) {
    return __fdividef(1.f, 1.f + __expf(-x));
}

// ---------------- W -> fp16 for layers 1..3 ----------------
__global__ void round_wh(const float* __restrict__ W, __half* __restrict__ Wh) {
    const size_t i = (size_t)blockIdx.x * 256 + threadIdx.x;
    Wh[i] = __float2half_rn(W[(size_t)Hdim * N3H + i]);
}

// ---------------- layer-0 GEMV partials (fp32) ----------------
__global__ void gemv_partial(const float* __restrict__ inp, const float* __restrict__ W0) {
    const int k = blockIdx.x * 128 + threadIdx.x;
    const int h0 = blockIdx.y * 128;
    float s = 0.f;
#pragma unroll 8
    for (int h = 0; h < 128; h++)
        s = fmaf(inp[h0 + h], W0[(size_t)(h0 + h) * N3H + k], s);
    g_U0p[blockIdx.y * N3H + k] = s;
}

// ---------------- fp16 mma.sync GEMM, K-chunk 64, fp16 C store ----------------
// C[M,N] = A[M,K] * B[K,N];  M=32768, N=3072, K=1024; A,B,C fp16 (fp32 accum).
#define A_ST  72                  // halfs per A smem row (64 + 8 pad) = 144 B
#define B_ST  136                 // halfs per B smem row (128 + 8 pad) = 272 B
#define A_STG (128 * A_ST)
#define B_STG (64 * B_ST)
#define GEMM_SMEM ((2 * A_STG + 2 * B_STG) * 2)   // 71680 bytes
#define KCH   16                  // 1024 / 64

__global__ void __launch_bounds__(256, 2) gemm_f16mma(
    const __half* __restrict__ A, const __half* __restrict__ B, __half* __restrict__ C)
{
    extern __shared__ __half sm[];
    __half* As = sm;                  // [2][128][72]
    __half* Bs = sm + 2 * A_STG;      // [2][64][136]
    const uint32_t sbA = smem_u32(As);
    const uint32_t sbB = smem_u32(Bs);

    const int tid = threadIdx.x;
    const int n0 = blockIdx.x * 128;
    const int m0 = blockIdx.y * 128;
    const int wid = tid >> 5, lane = tid & 31;
    const int wm = wid & 1, wn = wid >> 1;
    const int g = lane >> 2, tg = lane & 3;

    const __half* Ag = A + (size_t)m0 * 1024;
    const __half* Bg = B + n0;

    auto load_chunk = [&](int kc, int s) {
        const int koff = kc * 64;
#pragma unroll
        for (int i = 0; i < 4; i++) {
            const int idx = i * 256 + tid;
            const int row = idx >> 3, c16 = idx & 7;
            CP_ASYNC16(sbA + (s * A_STG + row * A_ST + c16 * 8) * 2,
                       Ag + (size_t)row * 1024 + koff + c16 * 8);
        }
#pragma unroll
        for (int i = 0; i < 4; i++) {
            const int idx = i * 256 + tid;
            const int row = idx >> 4, c16 = idx & 15;
            CP_ASYNC16(sbB + (s * B_STG + row * B_ST + c16 * 8) * 2,
                       Bg + (size_t)(koff + row) * N3H + c16 * 8);
        }
        CP_COMMIT();
    };

    const int a_row = wm * 64 + (lane & 15);
    const int a_kof = (lane >> 4) * 8;
    const int b_krow = (lane & 7) + ((lane >> 3) & 1) * 8;
    const int b_ncol = (lane >> 4) * 8;

    float acc[4][4][4];
#pragma unroll
    for (int i = 0; i < 4; i++)
#pragma unroll
        for (int j = 0; j < 4; j++)
#pragma unroll
            for (int q = 0; q < 4; q++) acc[i][j][q] = 0.f;

    load_chunk(0, 0);

    for (int c = 0; c < KCH; c++) {
        const int s = c & 1;
        if (c + 1 < KCH) load_chunk(c + 1, (c + 1) & 1);
        if (c + 1 < KCH) { CP_WAIT(1); } else { CP_WAIT(0); }
        __syncthreads();

#pragma unroll
        for (int ks = 0; ks < 4; ks++) {
            const int kb = ks * 16;
            uint32_t af[4][4], bf[4][2];
#pragma unroll
            for (int mt = 0; mt < 4; mt++) {
                const uint32_t addr = sbA +
                    (s * A_STG + (a_row + mt * 16) * A_ST + kb + a_kof) * 2;
                LDSM_X4(af[mt][0], af[mt][1], af[mt][2], af[mt][3], addr);
            }
#pragma unroll
            for (int nh = 0; nh < 2; nh++) {
                const uint32_t addr = sbB +
                    (s * B_STG + (kb + b_krow) * B_ST + wn * 32 + nh * 16 + b_ncol) * 2;
                LDSM_X4_T(bf[nh * 2][0], bf[nh * 2][1], bf[nh * 2 + 1][0], bf[nh * 2 + 1][1], addr);
            }
#pragma unroll
            for (int mt = 0; mt < 4; mt++)
#pragma unroll
                for (int nt = 0; nt < 4; nt++)
                    mma_f16(acc[mt][nt], af[mt], bf[nt]);
        }
        __syncthreads();
    }

    // fp16 epilogue (4B half2 stores)
#pragma unroll
    for (int mt = 0; mt < 4; mt++) {
        const int row = m0 + wm * 64 + mt * 16 + g;
        __half* Cp0 = C + (size_t)row * N3H + n0 + wn * 32 + 2 * tg;
        __half* Cp1 = Cp0 + (size_t)8 * N3H;
#pragma unroll
        for (int nt = 0; nt < 4; nt++) {
            *(__half2*)(Cp0 + nt * 8) = __floats2half2_rn(acc[mt][nt][0], acc[mt][nt][1]);
            *(__half2*)(Cp1 + nt * 8) = __floats2half2_rn(acc[mt][nt][2], acc[mt][nt][3]);
        }
    }
}

// ---------------- SRU scan (layers 1..3), fp16 U ----------------
#define UF 8
template <bool FINAL>
__global__ void __launch_bounds__(128) scan_pipelined(
    const __half* __restrict__ U, const float* __restrict__ Xin,
    const float* __restrict__ c0,
    const float* __restrict__ Vl, const float* __restrict__ bl,
    float* __restrict__ out, __half* __restrict__ outh)
{
    const int idx = blockIdx.x * 128 + threadIdx.x;   // < B*H
    const int b = idx >> 10;
    const int h = idx & 1023;

    float c  = c0[idx];
    const float vf = Vl[h], vr = Vl[Hdim + h];
    const float bf = bl[h], br = bl[Hdim + h];

    const __half* Ub = U   + (size_t)b * N3H + h;     // + t*(Bdim*N3H)
    const float*  Xb = Xin + (size_t)b * Hdim + h;    // + t*(Bdim*Hdim)

    float u0b[2][UF], u1b[2][UF], u2b[2][UF], xb[2][UF];

#define LOAD_BATCH(S, T0) do {                                               \
    _Pragma("unroll")                                                        \
    for (int i = 0; i < UF; i++) {                                           \
        const size_t tu = (size_t)((T0) + i) * (Bdim * N3H);                 \
        u0b[S][i] = __half2float(__ldg(Ub + tu));                            \
        u1b[S][i] = __half2float(__ldg(Ub + tu + Hdim));                     \
        u2b[S][i] = __half2float(__ldg(Ub + tu + 2 * Hdim));                 \
        xb[S][i]  = __ldg(Xb + (size_t)((T0) + i) * (Bdim * Hdim));          \
    }                                                                        \
} while (0)

#define COMPUTE_BATCH(S, T0) do {                                            \
    _Pragma("unroll")                                                        \
    for (int i = 0; i < UF; i++) {                                           \
        const int t = (T0) + i;                                              \
        const float f = fast_sigmoid(u1b[S][i] + vf * c + bf);               \
        c = f * c + (1.f - f) * u0b[S][i];                                   \
        const float r = fast_sigmoid(u2b[S][i] + vr * c + br);               \
        const float hv = r * c + (1.f - r) * xb[S][i];                       \
        const size_t oidx = FINAL ? ((size_t)b * Tlen + t) * Hdim + h        \
                                  : ((size_t)t * Bdim + b) * Hdim + h;       \
        out[oidx] = hv;                                                      \
        if (!FINAL) outh[oidx] = __float2half_rn(hv);                        \
    }                                                                        \
} while (0)

    LOAD_BATCH(0, 0);
    for (int t0 = 0; t0 < Tlen; t0 += 2 * UF) {
        LOAD_BATCH(1, t0 + UF);
        COMPUTE_BATCH(0, t0);
        if (t0 + 2 * UF < Tlen) LOAD_BATCH(0, t0 + 2 * UF);
        COMPUTE_BATCH(1, t0 + UF);
    }
#undef LOAD_BATCH
#undef COMPUTE_BATCH
}

// ---------------- layer-0 scan: broadcast inputs (fp32 path) ----------------
__global__ void __launch_bounds__(128) scan_l0(
    const float* __restrict__ U0p, const float* __restrict__ inp,
    const float* __restrict__ c0,
    const float* __restrict__ Vl, const float* __restrict__ bl,
    float* __restrict__ out, __half* __restrict__ outh)
{
    const int idx = blockIdx.x * 128 + threadIdx.x;
    const int b = idx >> 10;
    const int h = idx & 1023;

    float c  = c0[idx];
    const float vf = Vl[h], vr = Vl[Hdim + h];
    const float bf = bl[h], br = bl[Hdim + h];

    float u0 = 0.f, u1 = 0.f, u2 = 0.f;
#pragma unroll
    for (int p = 0; p < 8; p++) {
        u0 += U0p[p * N3H + h];
        u1 += U0p[p * N3H + Hdim + h];
        u2 += U0p[p * N3H + 2 * Hdim + h];
    }
    const float xt = inp[h];

#pragma unroll 8
    for (int t = 0; t < Tlen; t++) {
        const float f = fast_sigmoid(u1 + vf * c + bf);
        c = f * c + (1.f - f) * u0;
        const float r = fast_sigmoid(u2 + vr * c + br);
        const float hv = r * c + (1.f - r) * xt;
        const size_t oidx = ((size_t)t * Bdim + b) * Hdim + h;
        out[oidx] = hv;
        outh[oidx] = __float2half_rn(hv);
    }
}

// ---------------------------------------------------------------------------
extern "C" void kernel_launch(void* const* d_in, const int* in_sizes, int n_in,
                              void* d_out, int out_size)
{
    const float* c_n  = (const float*)d_in[0];
    const float* inp  = (const float*)d_in[2];
    const float* W    = (const float*)d_in[3];
    const float* V    = (const float*)d_in[4];
    const float* bias = (const float*)d_in[5];
    float* out = (float*)d_out;

    float *pX0, *pX1, *pU0p;
    __half *pUh, *pXh0, *pXh1, *pWh;
    cudaGetSymbolAddress((void**)&pUh,  g_Uh);
    cudaGetSymbolAddress((void**)&pX0,  g_X0);
    cudaGetSymbolAddress((void**)&pX1,  g_X1);
    cudaGetSymbolAddress((void**)&pXh0, g_Xh0);
    cudaGetSymbolAddress((void**)&pXh1, g_Xh1);
    cudaGetSymbolAddress((void**)&pWh,  g_Wh);
    cudaGetSymbolAddress((void**)&pU0p, g_U0p);

    cudaFuncSetAttribute(gemm_f16mma, cudaFuncAttributeMaxDynamicSharedMemorySize, GEMM_SMEM);

    // launch 0
    round_wh<<<(3 * Hdim * N3H) / 256, 256>>>(W, pWh);
    // launch 1
    gemv_partial<<<dim3(N3H / 128, 8), 128>>>(inp, W);
    // launch 2
    scan_l0<<<(Bdim * Hdim) / 128, 128>>>(pU0p, inp, c_n, V, bias, pX0, pXh0);

    const float*  xin  = pX0;   // fp32 highway input
    const __half* xinh = pXh0;  // fp16 GEMM A
    float*  xout  = pX1;
    __half* xouth = pXh1;
    for (int l = 1; l < NLay; l++) {
        // launches 3, 5, 7 — ncu -s 5 lands on the l=2 GEMM
        gemm_f16mma<<<dim3(N3H / 128, Mrows / 128), 256, GEMM_SMEM>>>(
            xinh, pWh + (size_t)(l - 1) * Hdim * N3H, pUh);
        const float* Vl = V + (size_t)l * 2 * Hdim;
        const float* bl = bias + (size_t)l * 2 * Hdim;
        if (l == NLay - 1) {
            scan_pipelined<true><<<(Bdim * Hdim) / 128, 128>>>(pUh, xin, c_n, Vl, bl, out, nullptr);
        } else {
            scan_pipelined<false><<<(Bdim * Hdim) / 128, 128>>>(pUh, xin, c_n, Vl, bl, xout, xouth);
            const float* t;
            t = xin; xin = xout; xout = (float*)t;
            const __half* th;
            th = xinh; xinh = xouth; xouth = (__half*)th;
        }
    }
}

// round 14
// speedup vs baseline: 6.7975x; 1.1523x over previous
#include <cuda_runtime.h>
#include <cuda_fp16.h>
#include <cstdint>
#include <math.h>

#define Tlen 2048
#define Bdim 16
#define Hdim 1024
#define NLay 4
#define N3H  3072
#define Mrows (Tlen * Bdim)      // 32768

// ---------------- device scratch (no allocs allowed) ----------------
__device__ __half g_Uh [(size_t)Mrows * N3H];       // U = x @ W_l (fp16)
__device__ float  g_X0 [(size_t)Mrows * Hdim];      // fp32 x ping (highway)
__device__ float  g_X1 [(size_t)Mrows * Hdim];      // fp32 x pong
__device__ __half g_Xh0[(size_t)Mrows * Hdim];      // fp16 x ping (GEMM A)
__device__ __half g_Xh1[(size_t)Mrows * Hdim];      // fp16 x pong
__device__ __half g_Wh [(size_t)3 * Hdim * N3H];    // fp16 W[1..3]
__device__ float  g_U0p[8 * N3H];                    // layer-0 gemv partials (fp32)

// ---------------- PTX helpers ----------------
__device__ __forceinline__ uint32_t smem_u32(const void* p) {
    uint32_t a;
    asm("{ .reg .u64 t; cvta.to.shared.u64 t, %1; cvt.u32.u64 %0, t; }" : "=r"(a) : "l"(p));
    return a;
}
#define CP_ASYNC16(dst, src) \
    asm volatile("cp.async.cg.shared.global [%0], [%1], 16;" :: "r"(dst), "l"(src) : "memory")
#define CP_COMMIT()   asm volatile("cp.async.commit_group;" ::: "memory")
#define CP_WAIT(n)    asm volatile("cp.async.wait_group %0;" :: "n"(n) : "memory")

#define LDSM_X4(r0, r1, r2, r3, a) \
    asm volatile("ldmatrix.sync.aligned.m8n8.x4.shared.b16 {%0,%1,%2,%3}, [%4];" \
                 : "=r"(r0), "=r"(r1), "=r"(r2), "=r"(r3) : "r"(a))
#define LDSM_X4_T(r0, r1, r2, r3, a) \
    asm volatile("ldmatrix.sync.aligned.m8n8.x4.trans.shared.b16 {%0,%1,%2,%3}, [%4];" \
                 : "=r"(r0), "=r"(r1), "=r"(r2), "=r"(r3) : "r"(a))

__device__ __forceinline__ void mma_f16(float* d, const uint32_t* a, const uint32_t* b) {
    asm volatile(
        "mma.sync.aligned.m16n8k16.row.col.f32.f16.f16.f32 "
        "{%0,%1,%2,%3}, {%4,%5,%6,%7}, {%8,%9}, {%0,%1,%2,%3};"
        : "+f"(d[0]), "+f"(d[1]), "+f"(d[2]), "+f"(d[3])
        : "r"(a[0]), "r"(a[1]), "r"(a[2]), "r"(a[3]), "r"(b[0]), "r"(b[1]));
}

// Single-MUFU tanh (sm_75+): the heart of the shortened sigmoid chain.
__device__ __forceinline__ float tanh_approx(float x) {
    float y;
    asm("tanh.approx.f32 %0, %1;" : "=f"(y) : "f"(x));
    return y;
}

// ---------------- W -> fp16 for layers 1..3 ----------------
__global__ void round_wh(const float* __restrict__ W, __half* __restrict__ Wh) {
    const size_t i = (size_t)blockIdx.x * 256 + threadIdx.x;
    Wh[i] = __float2half_rn(W[(size_t)Hdim * N3H + i]);
}

// ---------------- layer-0 GEMV partials (fp32) ----------------
__global__ void gemv_partial(const float* __restrict__ inp, const float* __restrict__ W0) {
    const int k = blockIdx.x * 128 + threadIdx.x;
    const int h0 = blockIdx.y * 128;
    float s = 0.f;
#pragma unroll 8
    for (int h = 0; h < 128; h++)
        s = fmaf(inp[h0 + h], W0[(size_t)(h0 + h) * N3H + k], s);
    g_U0p[blockIdx.y * N3H + k] = s;
}

// ---------------- fp16 mma.sync GEMM, K-chunk 64, fp16 C store ----------------
#define A_ST  72
#define B_ST  136
#define A_STG (128 * A_ST)
#define B_STG (64 * B_ST)
#define GEMM_SMEM ((2 * A_STG + 2 * B_STG) * 2)   // 71680 bytes
#define KCH   16

__global__ void __launch_bounds__(256, 2) gemm_f16mma(
    const __half* __restrict__ A, const __half* __restrict__ B, __half* __restrict__ C)
{
    extern __shared__ __half sm[];
    __half* As = sm;
    __half* Bs = sm + 2 * A_STG;
    const uint32_t sbA = smem_u32(As);
    const uint32_t sbB = smem_u32(Bs);

    const int tid = threadIdx.x;
    const int n0 = blockIdx.x * 128;
    const int m0 = blockIdx.y * 128;
    const int wid = tid >> 5, lane = tid & 31;
    const int wm = wid & 1, wn = wid >> 1;
    const int g = lane >> 2, tg = lane & 3;

    const __half* Ag = A + (size_t)m0 * 1024;
    const __half* Bg = B + n0;

    auto load_chunk = [&](int kc, int s) {
        const int koff = kc * 64;
#pragma unroll
        for (int i = 0; i < 4; i++) {
            const int idx = i * 256 + tid;
            const int row = idx >> 3, c16 = idx & 7;
            CP_ASYNC16(sbA + (s * A_STG + row * A_ST + c16 * 8) * 2,
                       Ag + (size_t)row * 1024 + koff + c16 * 8);
        }
#pragma unroll
        for (int i = 0; i < 4; i++) {
            const int idx = i * 256 + tid;
            const int row = idx >> 4, c16 = idx & 15;
            CP_ASYNC16(sbB + (s * B_STG + row * B_ST + c16 * 8) * 2,
                       Bg + (size_t)(koff + row) * N3H + c16 * 8);
        }
        CP_COMMIT();
    };

    const int a_row = wm * 64 + (lane & 15);
    const int a_kof = (lane >> 4) * 8;
    const int b_krow = (lane & 7) + ((lane >> 3) & 1) * 8;
    const int b_ncol = (lane >> 4) * 8;

    float acc[4][4][4];
#pragma unroll
    for (int i = 0; i < 4; i++)
#pragma unroll
        for (int j = 0; j < 4; j++)
#pragma unroll
            for (int q = 0; q < 4; q++) acc[i][j][q] = 0.f;

    load_chunk(0, 0);

    for (int c = 0; c < KCH; c++) {
        const int s = c & 1;
        if (c + 1 < KCH) load_chunk(c + 1, (c + 1) & 1);
        if (c + 1 < KCH) { CP_WAIT(1); } else { CP_WAIT(0); }
        __syncthreads();

#pragma unroll
        for (int ks = 0; ks < 4; ks++) {
            const int kb = ks * 16;
            uint32_t af[4][4], bf[4][2];
#pragma unroll
            for (int mt = 0; mt < 4; mt++) {
                const uint32_t addr = sbA +
                    (s * A_STG + (a_row + mt * 16) * A_ST + kb + a_kof) * 2;
                LDSM_X4(af[mt][0], af[mt][1], af[mt][2], af[mt][3], addr);
            }
#pragma unroll
            for (int nh = 0; nh < 2; nh++) {
                const uint32_t addr = sbB +
                    (s * B_STG + (kb + b_krow) * B_ST + wn * 32 + nh * 16 + b_ncol) * 2;
                LDSM_X4_T(bf[nh * 2][0], bf[nh * 2][1], bf[nh * 2 + 1][0], bf[nh * 2 + 1][1], addr);
            }
#pragma unroll
            for (int mt = 0; mt < 4; mt++)
#pragma unroll
                for (int nt = 0; nt < 4; nt++)
                    mma_f16(acc[mt][nt], af[mt], bf[nt]);
        }
        __syncthreads();
    }

#pragma unroll
    for (int mt = 0; mt < 4; mt++) {
        const int row = m0 + wm * 64 + mt * 16 + g;
        __half* Cp0 = C + (size_t)row * N3H + n0 + wn * 32 + 2 * tg;
        __half* Cp1 = Cp0 + (size_t)8 * N3H;
#pragma unroll
        for (int nt = 0; nt < 4; nt++) {
            *(__half2*)(Cp0 + nt * 8) = __floats2half2_rn(acc[mt][nt][0], acc[mt][nt][1]);
            *(__half2*)(Cp1 + nt * 8) = __floats2half2_rn(acc[mt][nt][2], acc[mt][nt][3]);
        }
    }
}

// ---------------- SRU scan (layers 1..3), fp16 U, tanh-based gates ----------
// sigma(x) = 0.5*(1 + tanh(x/2)). All 0.5-factors folded so the serial
// c-chain is: fma -> TANH (MUFU) -> fma  (~24 cyc vs ~60 for exp+div).
#define UF 8
template <bool FINAL>
__global__ void __launch_bounds__(128) scan_pipelined(
    const __half* __restrict__ U, const float* __restrict__ Xin,
    const float* __restrict__ c0,
    const float* __restrict__ Vl, const float* __restrict__ bl,
    float* __restrict__ out, __half* __restrict__ outh)
{
    const int idx = blockIdx.x * 128 + threadIdx.x;   // < B*H
    const int b = idx >> 10;
    const int h = idx & 1023;

    float c  = c0[idx];
    const float hvf = 0.5f * Vl[h],        hvr = 0.5f * Vl[Hdim + h];
    const float hbf = 0.5f * bl[h],        hbr = 0.5f * bl[Hdim + h];

    const __half* Ub = U   + (size_t)b * N3H + h;
    const float*  Xb = Xin + (size_t)b * Hdim + h;

    // staged (off-chain) values: p1 = 0.5*u1 + 0.5*bf, p2 = 0.5*u2 + 0.5*br,
    // su = 0.5*u0, sx = 0.5*x
    float p1b[2][UF], p2b[2][UF], sub[2][UF], sxb[2][UF];

#define LOAD_BATCH(S, T0) do {                                               \
    _Pragma("unroll")                                                        \
    for (int i = 0; i < UF; i++) {                                           \
        const size_t tu = (size_t)((T0) + i) * (Bdim * N3H);                 \
        sub[S][i] = 0.5f * __half2float(__ldg(Ub + tu));                     \
        p1b[S][i] = fmaf(0.5f, __half2float(__ldg(Ub + tu + Hdim)), hbf);    \
        p2b[S][i] = fmaf(0.5f, __half2float(__ldg(Ub + tu + 2 * Hdim)), hbr);\
        sxb[S][i] = 0.5f * __ldg(Xb + (size_t)((T0) + i) * (Bdim * Hdim));   \
    }                                                                        \
} while (0)

#define COMPUTE_BATCH(S, T0) do {                                            \
    _Pragma("unroll")                                                        \
    for (int i = 0; i < UF; i++) {                                           \
        const int t = (T0) + i;                                              \
        const float Tf = tanh_approx(fmaf(hvf, c, p1b[S][i]));               \
        const float Af = fmaf(0.5f, c,  sub[S][i]);                          \
        const float Bf = fmaf(0.5f, c, -sub[S][i]);                          \
        c = fmaf(Tf, Bf, Af);                                                \
        const float Tr = tanh_approx(fmaf(hvr, c, p2b[S][i]));               \
        const float Ar = fmaf(0.5f, c,  sxb[S][i]);                          \
        const float Br = fmaf(0.5f, c, -sxb[S][i]);                          \
        const float hv = fmaf(Tr, Br, Ar);                                   \
        const size_t oidx = FINAL ? ((size_t)b * Tlen + t) * Hdim + h        \
                                  : ((size_t)t * Bdim + b) * Hdim + h;       \
        out[oidx] = hv;                                                      \
        if (!FINAL) outh[oidx] = __float2half_rn(hv);                        \
    }                                                                        \
} while (0)

    LOAD_BATCH(0, 0);
    for (int t0 = 0; t0 < Tlen; t0 += 2 * UF) {
        LOAD_BATCH(1, t0 + UF);
        COMPUTE_BATCH(0, t0);
        if (t0 + 2 * UF < Tlen) LOAD_BATCH(0, t0 + 2 * UF);
        COMPUTE_BATCH(1, t0 + UF);
    }
#undef LOAD_BATCH
#undef COMPUTE_BATCH
}

// ---------------- layer-0 scan: broadcast inputs, tanh gates ----------------
__global__ void __launch_bounds__(128) scan_l0(
    const float* __restrict__ U0p, const float* __restrict__ inp,
    const float* __restrict__ c0,
    const float* __restrict__ Vl, const float* __restrict__ bl,
    float* __restrict__ out, __half* __restrict__ outh)
{
    const int idx = blockIdx.x * 128 + threadIdx.x;
    const int b = idx >> 10;
    const int h = idx & 1023;

    float c  = c0[idx];
    const float hvf = 0.5f * Vl[h],  hvr = 0.5f * Vl[Hdim + h];
    const float hbf = 0.5f * bl[h],  hbr = 0.5f * bl[Hdim + h];

    float u0 = 0.f, u1 = 0.f, u2 = 0.f;
#pragma unroll
    for (int p = 0; p < 8; p++) {
        u0 += U0p[p * N3H + h];
        u1 += U0p[p * N3H + Hdim + h];
        u2 += U0p[p * N3H + 2 * Hdim + h];
    }
    const float su = 0.5f * u0;
    const float p1 = fmaf(0.5f, u1, hbf);
    const float p2 = fmaf(0.5f, u2, hbr);
    const float sx = 0.5f * inp[h];

#pragma unroll 8
    for (int t = 0; t < Tlen; t++) {
        const float Tf = tanh_approx(fmaf(hvf, c, p1));
        const float Af = fmaf(0.5f, c,  su);
        const float Bf = fmaf(0.5f, c, -su);
        c = fmaf(Tf, Bf, Af);
        const float Tr = tanh_approx(fmaf(hvr, c, p2));
        const float Ar = fmaf(0.5f, c,  sx);
        const float Br = fmaf(0.5f, c, -sx);
        const float hv = fmaf(Tr, Br, Ar);
        const size_t oidx = ((size_t)t * Bdim + b) * Hdim + h;
        out[oidx] = hv;
        outh[oidx] = __float2half_rn(hv);
    }
}

// ---------------------------------------------------------------------------
extern "C" void kernel_launch(void* const* d_in, const int* in_sizes, int n_in,
                              void* d_out, int out_size)
{
    const float* c_n  = (const float*)d_in[0];
    const float* inp  = (const float*)d_in[2];
    const float* W    = (const float*)d_in[3];
    const float* V    = (const float*)d_in[4];
    const float* bias = (const float*)d_in[5];
    float* out = (float*)d_out;

    float *pX0, *pX1, *pU0p;
    __half *pUh, *pXh0, *pXh1, *pWh;
    cudaGetSymbolAddress((void**)&pUh,  g_Uh);
    cudaGetSymbolAddress((void**)&pX0,  g_X0);
    cudaGetSymbolAddress((void**)&pX1,  g_X1);
    cudaGetSymbolAddress((void**)&pXh0, g_Xh0);
    cudaGetSymbolAddress((void**)&pXh1, g_Xh1);
    cudaGetSymbolAddress((void**)&pWh,  g_Wh);
    cudaGetSymbolAddress((void**)&pU0p, g_U0p);

    cudaFuncSetAttribute(gemm_f16mma, cudaFuncAttributeMaxDynamicSharedMemorySize, GEMM_SMEM);

    // launch 0
    round_wh<<<(3 * Hdim * N3H) / 256, 256>>>(W, pWh);
    // launch 1
    gemv_partial<<<dim3(N3H / 128, 8), 128>>>(inp, W);
    // launch 2
    scan_l0<<<(Bdim * Hdim) / 128, 128>>>(pU0p, inp, c_n, V, bias, pX0, pXh0);

    const float*  xin  = pX0;
    const __half* xinh = pXh0;
    float*  xout  = pX1;
    __half* xouth = pXh1;
    for (int l = 1; l < NLay; l++) {
        // launches 3, 5, 7 — ncu -s 5 lands on the l=2 GEMM
        gemm_f16mma<<<dim3(N3H / 128, Mrows / 128), 256, GEMM_SMEM>>>(
            xinh, pWh + (size_t)(l - 1) * Hdim * N3H, pUh);
        const float* Vl = V + (size_t)l * 2 * Hdim;
        const float* bl = bias + (size_t)l * 2 * Hdim;
        if (l == NLay - 1) {
            scan_pipelined<true><<<(Bdim * Hdim) / 128, 128>>>(pUh, xin, c_n, Vl, bl, out, nullptr);
        } else {
            scan_pipelined<false><<<(Bdim * Hdim) / 128, 128>>>(pUh, xin, c_n, Vl, bl, xout, xouth);
            const float* t;
            t = xin; xin = xout; xout = (float*)t;
            const __half* th;
            th = xinh; xinh = xouth; xouth = (__half*)th;
        }
    }
}